// round 2
// baseline (speedup 1.0000x reference)
#include <cuda_runtime.h>
#include <math.h>
#include <stdint.h>

// Problem constants
#define BATCH 16
#define LDIM  1024
#define SDIM  256
#define EPS_BN 1e-3f

#define SEQ_ELEMS (BATCH * LDIM * SDIM)          // 4,194,304 floats (16 MB)
#define MAT_ELEMS ((size_t)BATCH * LDIM * LDIM)  // 16,777,216 floats (64 MB)

// Scratch (device globals: allocation-free, graph-capture safe)
__device__ float g_h [SEQ_ELEMS];
__device__ float g_k1[SEQ_ELEMS];
__device__ float g_q1[SEQ_ELEMS];
__device__ float g_v1[SEQ_ELEMS];
__device__ float g_k2[SEQ_ELEMS];
__device__ float g_q2[SEQ_ELEMS];
__device__ float g_v2[SEQ_ELEMS];
__device__ float g_w1[MAT_ELEMS];
__device__ float g_w2[MAT_ELEMS];
__device__ float g_ap1[SEQ_ELEMS];
__device__ float g_ap2[SEQ_ELEMS];

// ---------------------------------------------------------------------------
// Generic tiled fp32 GEMM: C[b] = epilogue(op(A[b]) @ op(B[b]))
//   AT=false: A is [M,K] row-major.   AT=true: A is [K,M] row-major (lda=M).
//   BT=false: B is [K,N] row-major.   BT=true: B is [N,K] row-major (ldb=K).
// Tile: 64x64x16, 256 threads, 4x4 per-thread micro-tile.
// All dims used here are multiples of 64 -> no bounds checks.
// Smem rows padded to 68 floats (16B-aligned rows -> LDS.128 for fragments).
// Epilogue order: +bias -> *mul*scale -> relu -> batchnorm
// ---------------------------------------------------------------------------
template<bool AT, bool BT, int MULMODE, bool BIAS, bool RELU, bool BNORM>
__global__ __launch_bounds__(256)
void gemm_kernel(const float* __restrict__ A, size_t aStride,
                 const float* __restrict__ Bm, size_t bStride,
                 float* __restrict__ C, size_t cStride,
                 int M, int N, int K,
                 const float* __restrict__ bias,
                 const float* __restrict__ mul, size_t mulStride, int ldm, float mulScale,
                 const float* __restrict__ gamma, const float* __restrict__ beta,
                 const float* __restrict__ mean, const float* __restrict__ var)
{
    __shared__ __align__(16) float As[16][68];
    __shared__ __align__(16) float Bs[16][68];

    const int b = blockIdx.z;
    A  += (size_t)b * aStride;
    Bm += (size_t)b * bStride;
    C  += (size_t)b * cStride;
    if (MULMODE) mul += (size_t)b * mulStride;

    const int m0 = blockIdx.y * 64;
    const int n0 = blockIdx.x * 64;
    const int tid = threadIdx.x;
    const int tx = tid & 15;        // 0..15 -> 4 output columns
    const int ty = tid >> 4;        // 0..15 -> 4 output rows

    float acc[4][4] = {};

    for (int k0 = 0; k0 < K; k0 += 16) {
        // ---- load A tile (64 rows x 16 k) into As[k][m] ----
        #pragma unroll
        for (int i = 0; i < 4; i++) {
            int idx = tid + i * 256;
            if (!AT) {
                int m = idx >> 4, k = idx & 15;
                As[k][m] = A[(size_t)(m0 + m) * K + (k0 + k)];
            } else {
                int k = idx >> 6, m = idx & 63;
                As[k][m] = A[(size_t)(k0 + k) * M + (m0 + m)];
            }
        }
        // ---- load B tile (16 k x 64 cols) into Bs[k][n] ----
        #pragma unroll
        for (int i = 0; i < 4; i++) {
            int idx = tid + i * 256;
            if (!BT) {
                int k = idx >> 6, n = idx & 63;
                Bs[k][n] = Bm[(size_t)(k0 + k) * N + (n0 + n)];
            } else {
                int n = idx >> 4, k = idx & 15;
                Bs[k][n] = Bm[(size_t)(n0 + n) * K + (k0 + k)];
            }
        }
        __syncthreads();

        #pragma unroll
        for (int kk = 0; kk < 16; kk++) {
            float4 a  = *reinterpret_cast<const float4*>(&As[kk][ty * 4]);
            float4 bb = *reinterpret_cast<const float4*>(&Bs[kk][tx * 4]);
            float av[4] = {a.x, a.y, a.z, a.w};
            float bv[4] = {bb.x, bb.y, bb.z, bb.w};
            #pragma unroll
            for (int i = 0; i < 4; i++)
                #pragma unroll
                for (int j = 0; j < 4; j++)
                    acc[i][j] += av[i] * bv[j];
        }
        __syncthreads();
    }

    #pragma unroll
    for (int i = 0; i < 4; i++) {
        int row = m0 + ty * 4 + i;
        #pragma unroll
        for (int j = 0; j < 4; j++) {
            int col = n0 + tx * 4 + j;
            float v = acc[i][j];
            if (BIAS)         v += bias[col];
            if (MULMODE == 1) v *= mul[(size_t)row * ldm + col] * mulScale;
            if (MULMODE == 2) v *= mul[(size_t)col * ldm + row] * mulScale;
            if (RELU)         v = fmaxf(v, 0.0f);
            if (BNORM) {
                float sc = gamma[col] * rsqrtf(var[col] + EPS_BN);
                v = (v - mean[col]) * sc + beta[col];
            }
            C[(size_t)row * N + col] = v;
        }
    }
}

// ---------------------------------------------------------------------------
// In-place softmax over axis 1 of w[B, L, L] (over the ROW index l, for each
// column m). Each thread owns one column; loads are coalesced across threads.
// Online max+sum pass, then a normalize pass.
// ---------------------------------------------------------------------------
__global__ __launch_bounds__(256)
void softmax_axis1_kernel(float* __restrict__ w)
{
    const int b   = blockIdx.z;
    const int col = blockIdx.x * blockDim.x + threadIdx.x;
    float* base = w + (size_t)b * LDIM * LDIM + col;

    float mx = -1e30f, sum = 0.0f;
    for (int l = 0; l < LDIM; l++) {
        float x = base[(size_t)l * LDIM];
        if (x > mx) {
            sum = sum * __expf(mx - x) + 1.0f;
            mx = x;
        } else {
            sum += __expf(x - mx);
        }
    }
    float inv = 1.0f / sum;
    for (int l = 0; l < LDIM; l++) {
        size_t o = (size_t)l * LDIM;
        base[o] = __expf(base[o] - mx) * inv;
    }
}

// ---------------------------------------------------------------------------
// Host-side launch helpers
// ---------------------------------------------------------------------------
static inline void launch_nn(const float* A, const float* W, const float* bias,
                             float* C, bool relu)
{
    // Flattened over batch: M = BATCH*LDIM, N = SDIM, K = 256
    dim3 grid(SDIM / 64, (BATCH * LDIM) / 64, 1);
    if (relu)
        gemm_kernel<false, false, 0, true, true, false><<<grid, 256>>>(
            A, 0, W, 0, C, 0, BATCH * LDIM, SDIM, 256,
            bias, nullptr, 0, 0, 0.f, nullptr, nullptr, nullptr, nullptr);
    else
        gemm_kernel<false, false, 0, true, false, false><<<grid, 256>>>(
            A, 0, W, 0, C, 0, BATCH * LDIM, SDIM, 256,
            bias, nullptr, 0, 0, 0.f, nullptr, nullptr, nullptr, nullptr);
}

extern "C" void kernel_launch(void* const* d_in, const int* in_sizes, int n_in,
                              void* d_out, int out_size)
{
    const float* seq1  = (const float*)d_in[0];
    const float* seq2  = (const float*)d_in[1];
    const float* disto = (const float*)d_in[2];
    const float* kW1 = (const float*)d_in[3];  const float* kb1 = (const float*)d_in[4];
    const float* kW2 = (const float*)d_in[5];  const float* kb2 = (const float*)d_in[6];
    const float* qW1 = (const float*)d_in[7];  const float* qb1 = (const float*)d_in[8];
    const float* qW2 = (const float*)d_in[9];  const float* qb2 = (const float*)d_in[10];
    const float* vW1 = (const float*)d_in[11]; const float* vb1 = (const float*)d_in[12];
    const float* vW2 = (const float*)d_in[13]; const float* vb2 = (const float*)d_in[14];
    const float* fc1W = (const float*)d_in[15]; const float* fc1b = (const float*)d_in[16];
    const float* fc2W = (const float*)d_in[17]; const float* fc2b = (const float*)d_in[18];
    const float* gma  = (const float*)d_in[19]; const float* bta  = (const float*)d_in[20];
    const float* mean = (const float*)d_in[21]; const float* var  = (const float*)d_in[22];
    float* out = (float*)d_out;

    float *h, *k1, *q1, *v1, *k2, *q2, *v2, *w1, *w2, *ap1, *ap2;
    cudaGetSymbolAddress((void**)&h,  g_h);
    cudaGetSymbolAddress((void**)&k1, g_k1);
    cudaGetSymbolAddress((void**)&q1, g_q1);
    cudaGetSymbolAddress((void**)&v1, g_v1);
    cudaGetSymbolAddress((void**)&k2, g_k2);
    cudaGetSymbolAddress((void**)&q2, g_q2);
    cudaGetSymbolAddress((void**)&v2, g_v2);
    cudaGetSymbolAddress((void**)&w1, g_w1);
    cudaGetSymbolAddress((void**)&w2, g_w2);
    cudaGetSymbolAddress((void**)&ap1, g_ap1);
    cudaGetSymbolAddress((void**)&ap2, g_ap2);

    // ---- 6 shared-weight MLPs (2 GEMMs each), batch flattened ----
    launch_nn(seq1, kW1, kb1, h, true);  launch_nn(h, kW2, kb2, k1, false);
    launch_nn(seq1, qW1, qb1, h, true);  launch_nn(h, qW2, qb2, q1, false);
    launch_nn(seq1, vW1, vb1, h, true);  launch_nn(h, vW2, vb2, v1, false);
    launch_nn(seq2, kW1, kb1, h, true);  launch_nn(h, kW2, kb2, k2, false);
    launch_nn(seq2, qW1, qb1, h, true);  launch_nn(h, qW2, qb2, q2, false);
    launch_nn(seq2, vW1, vb1, h, true);  launch_nn(h, vW2, vb2, v2, false);

    const float invS = 1.0f / 256.0f;
    const size_t seqB = (size_t)LDIM * SDIM;   // per-batch stride of [L,S] tensors
    const size_t matB = (size_t)LDIM * LDIM;   // per-batch stride of [L,L] tensors

    // ---- scores1[b,l,m] = (q1[b,l,:].k2[b,m,:]) * disto[b,l,m]/256 ----
    {
        dim3 grid(LDIM / 64, LDIM / 64, BATCH);
        gemm_kernel<false, true, 1, false, false, false><<<grid, 256>>>(
            q1, seqB, k2, seqB, w1, matB, LDIM, LDIM, SDIM,
            nullptr, disto, matB, LDIM, invS, nullptr, nullptr, nullptr, nullptr);
    }
    // ---- scores2[b,m,l] = (q2[b,m,:].k1[b,l,:]) * disto[b,l,m]/256 ----
    {
        dim3 grid(LDIM / 64, LDIM / 64, BATCH);
        gemm_kernel<false, true, 2, false, false, false><<<grid, 256>>>(
            q2, seqB, k1, seqB, w2, matB, LDIM, LDIM, SDIM,
            nullptr, disto, matB, LDIM, invS, nullptr, nullptr, nullptr, nullptr);
    }

    // ---- softmax over axis 1 (rows), in place ----
    {
        dim3 grid(LDIM / 256, 1, BATCH);
        softmax_axis1_kernel<<<grid, 256>>>(w1);
        softmax_axis1_kernel<<<grid, 256>>>(w2);
    }

    // ---- ap1[b,m,s] = sum_l w1[b,l,m] * v1[b,l,s]  (A^T GEMM, K=1024) ----
    {
        dim3 grid(SDIM / 64, LDIM / 64, BATCH);
        gemm_kernel<true, false, 0, false, false, false><<<grid, 256>>>(
            w1, matB, v1, seqB, ap1, seqB, LDIM, SDIM, LDIM,
            nullptr, nullptr, 0, 0, 0.f, nullptr, nullptr, nullptr, nullptr);
        gemm_kernel<true, false, 0, false, false, false><<<grid, 256>>>(
            w2, matB, v2, seqB, ap2, seqB, LDIM, SDIM, LDIM,
            nullptr, nullptr, 0, 0, 0.f, nullptr, nullptr, nullptr, nullptr);
    }

    // ---- out = bn(relu(ap @ fcW + fcb)), flattened over batch ----
    {
        dim3 grid(SDIM / 64, (BATCH * LDIM) / 64, 1);
        gemm_kernel<false, false, 0, true, true, true><<<grid, 256>>>(
            ap1, 0, fc1W, 0, out, 0, BATCH * LDIM, SDIM, 256,
            fc1b, nullptr, 0, 0, 0.f, gma, bta, mean, var);
        gemm_kernel<false, false, 0, true, true, true><<<grid, 256>>>(
            ap2, 0, fc2W, 0, out + (size_t)SEQ_ELEMS, 0, BATCH * LDIM, SDIM, 256,
            fc2b, nullptr, 0, 0, 0.f, gma, bta, mean, var);
    }
}

// round 5
// speedup vs baseline: 1.9696x; 1.9696x over previous
#include <cuda_runtime.h>
#include <cstdint>
#include <math.h>

// ---------------------------------------------------------------------------
// Problem constants
// ---------------------------------------------------------------------------
#define BATCH 16
#define LDIM  1024
#define SDIM  256
#define EPS_BN 1e-3f

#define SEQ_ELEMS (BATCH * LDIM * SDIM)          // 4,194,304 floats
#define MAT_ELEMS ((size_t)BATCH * LDIM * LDIM)  // 16,777,216 floats

// Scratch (device globals: allocation-free, graph-capture safe)
__device__ float g_h  [SEQ_ELEMS];
__device__ float g_k1 [SEQ_ELEMS];
__device__ float g_q1 [SEQ_ELEMS];
__device__ float g_v1 [SEQ_ELEMS];
__device__ float g_k2 [SEQ_ELEMS];
__device__ float g_q2 [SEQ_ELEMS];
__device__ float g_v2 [SEQ_ELEMS];
__device__ float g_w1 [MAT_ELEMS];   // s1t (transposed scores 1) -> softmaxed
__device__ float g_w2 [MAT_ELEMS];   // s2t
__device__ float g_ap1[SEQ_ELEMS];
__device__ float g_ap2[SEQ_ELEMS];
__device__ float g_v1T[SEQ_ELEMS];
__device__ float g_v2T[SEQ_ELEMS];
__device__ float g_dT [MAT_ELEMS];   // distogram transposed
__device__ float g_wT [8 * 256 * 256]; // transposed weight matrices

// ---------------------------------------------------------------------------
// tf32 round-to-nearest of fp32 (kept in 32-bit container)
// ---------------------------------------------------------------------------
__device__ __forceinline__ float tf32r(float x) {
    uint32_t u;
    asm("cvt.rna.tf32.f32 %0, %1;" : "=r"(u) : "f"(x));
    return __uint_as_float(u);
}

// ---------------------------------------------------------------------------
// Warp-level tf32 MMA GEMM: C[z][M,N] = epilogue( A[z][M,K] @ B[z][N,K]^T )
//
// CTA tile 128x128, K-chunk 32. 8 warps as 2(M) x 4(N); warp tile 64x32
// -> 4 m-tiles x 4 n-tiles of mma.sync.m16n8k8 (tf32), fp32 accum in regs.
//
// Smem layout per operand: for each row, 16 float2 "slots":
//   slot(s, c) holds ( X[row][8s+c], X[row][8s+c+4] ),  s=0..3, c=0..3,
//   stored at f2 index  row*17 + ((s ^ (row&3))<<2) + c   (pad+swizzle).
// A fragment = 2 x LDS.64 (rows g, g+8); B fragment = 1 x LDS.64.
//
// Double-buffered smem; global loads register-staged; 1 syncthreads/chunk.
// Epilogue: +bias -> *mul*mulScale -> relu -> batchnorm (template flags).
// Requires: M,N multiples of 128; K multiple of 32; row-major, tight.
// ---------------------------------------------------------------------------
#define GEMM_SMEM_BYTES (8704 * 8)   // 4 buffers (A0,B0,A1,B1) x 2176 float2

template<int MUL, bool BIAS, bool RELU, bool BN>
__global__ __launch_bounds__(256)
void gemm_mma(const float* __restrict__ A, size_t aB,
              const float* __restrict__ B, size_t bB,
              float* __restrict__ C, size_t cB,
              int M, int N, int K,
              const float* __restrict__ bias,
              const float* __restrict__ mul, size_t mulB, float mulScale,
              const float* __restrict__ gm, const float* __restrict__ bt,
              const float* __restrict__ mn, const float* __restrict__ vr)
{
    extern __shared__ float2 sm[];
    const int tid  = threadIdx.x;
    const int lane = tid & 31;
    const int wid  = tid >> 5;
    const int wm   = wid >> 2;            // 0..1  (64-row slab)
    const int wn   = wid & 3;             // 0..3  (32-col slab)
    const int z    = blockIdx.z;
    const int m0   = blockIdx.y * 128;
    const int n0   = blockIdx.x * 128;

    A += (size_t)z * aB + (size_t)m0 * K;
    B += (size_t)z * bB + (size_t)n0 * K;
    C += (size_t)z * cB;
    if (MUL) mul += (size_t)z * mulB;

    float2* Abuf[2] = { sm,            sm + 4352 };
    float2* Bbuf[2] = { sm + 2176,     sm + 6528 };

    // ---- store-phase constants (per thread) ----
    const int jj   = tid & 7;             // float4 index within a 32-k row
    const int r_lo = tid >> 3;            // 0..31 (row within 32-row block)
    const int s_st = jj >> 1;             // k-step of this float4
    const int h_st = jj & 1;              // low/high half of the pair
    const int slotbase = ((s_st ^ (r_lo & 3)) << 2);

    float acc[4][4][4];
    #pragma unroll
    for (int i = 0; i < 4; i++)
        #pragma unroll
        for (int j = 0; j < 4; j++)
            #pragma unroll
            for (int t = 0; t < 4; t++) acc[i][j][t] = 0.f;

    const int nch = K >> 5;
    float4 va[4], vb[4];

    // ---- gmem chunk load into registers ----
    #define LD_CHUNK(ck) do { \
        const float* Ak = A + (ck) * 32 + jj * 4; \
        const float* Bk = B + (ck) * 32 + jj * 4; \
        _Pragma("unroll") \
        for (int it = 0; it < 4; ++it) { \
            va[it] = *(const float4*)(Ak + (size_t)(it * 32 + r_lo) * K); \
            vb[it] = *(const float4*)(Bk + (size_t)(it * 32 + r_lo) * K); \
        } \
    } while (0)

    // ---- registers -> swizzled smem (tf32-rounded) ----
    #define STS_CHUNK(bp) do { \
        float* Af = (float*)(Abuf[bp]); \
        float* Bf = (float*)(Bbuf[bp]); \
        _Pragma("unroll") \
        for (int it = 0; it < 4; ++it) { \
            const int base = ((it * 32 + r_lo) * 17 + slotbase) * 2 + h_st; \
            Af[base + 0] = tf32r(va[it].x); Af[base + 2] = tf32r(va[it].y); \
            Af[base + 4] = tf32r(va[it].z); Af[base + 6] = tf32r(va[it].w); \
            Bf[base + 0] = tf32r(vb[it].x); Bf[base + 2] = tf32r(vb[it].y); \
            Bf[base + 4] = tf32r(vb[it].z); Bf[base + 6] = tf32r(vb[it].w); \
        } \
    } while (0)

    const int g  = lane >> 2;
    const int cc = lane & 3;

    LD_CHUNK(0);
    STS_CHUNK(0);
    __syncthreads();

    for (int ch = 0; ch < nch; ++ch) {
        if (ch + 1 < nch) LD_CHUNK(ch + 1);

        const float2* Ab = Abuf[ch & 1];
        const float2* Bb = Bbuf[ch & 1];
        #pragma unroll
        for (int s = 0; s < 4; ++s) {
            float2 af[4][2], bf[4];
            #pragma unroll
            for (int i = 0; i < 4; ++i) {
                const int rA = wm * 64 + i * 16 + g;
                const int sl = ((s ^ (rA & 3)) << 2) + cc;
                af[i][0] = Ab[rA * 17 + sl];
                af[i][1] = Ab[(rA + 8) * 17 + sl];
            }
            #pragma unroll
            for (int j = 0; j < 4; ++j) {
                const int rB = wn * 32 + j * 8 + g;
                const int sl = ((s ^ (rB & 3)) << 2) + cc;
                bf[j] = Bb[rB * 17 + sl];
            }
            #pragma unroll
            for (int i = 0; i < 4; ++i)
                #pragma unroll
                for (int j = 0; j < 4; ++j) {
                    asm volatile(
                        "mma.sync.aligned.m16n8k8.row.col.f32.tf32.tf32.f32 "
                        "{%0,%1,%2,%3}, {%4,%5,%6,%7}, {%8,%9}, {%0,%1,%2,%3};"
                        : "+f"(acc[i][j][0]), "+f"(acc[i][j][1]),
                          "+f"(acc[i][j][2]), "+f"(acc[i][j][3])
                        : "r"(__float_as_uint(af[i][0].x)), "r"(__float_as_uint(af[i][1].x)),
                          "r"(__float_as_uint(af[i][0].y)), "r"(__float_as_uint(af[i][1].y)),
                          "r"(__float_as_uint(bf[j].x)),    "r"(__float_as_uint(bf[j].y)));
                }
        }

        if (ch + 1 < nch) STS_CHUNK((ch + 1) & 1);
        __syncthreads();
    }
    #undef LD_CHUNK
    #undef STS_CHUNK

    // ---- epilogue: regs -> gmem (float2 stores) ----
    #pragma unroll
    for (int j = 0; j < 4; ++j) {
        const int col = n0 + wn * 32 + j * 8 + cc * 2;
        float2 b2, g2, be2, mn2, iv2;
        if (BIAS) b2 = *(const float2*)(bias + col);
        if (BN) {
            g2  = *(const float2*)(gm + col);
            be2 = *(const float2*)(bt + col);
            mn2 = *(const float2*)(mn + col);
            float2 v2 = *(const float2*)(vr + col);
            iv2 = make_float2(rsqrtf(v2.x + EPS_BN), rsqrtf(v2.y + EPS_BN));
        }
        #pragma unroll
        for (int i = 0; i < 4; ++i) {
            const int row0 = m0 + wm * 64 + i * 16 + g;
            #pragma unroll
            for (int hh = 0; hh < 2; ++hh) {
                const int row = row0 + hh * 8;
                float v0 = acc[i][j][hh * 2 + 0];
                float v1 = acc[i][j][hh * 2 + 1];
                if (BIAS) { v0 += b2.x; v1 += b2.y; }
                if (MUL) {
                    float2 m2 = *(const float2*)(mul + (size_t)row * N + col);
                    v0 *= m2.x * mulScale; v1 *= m2.y * mulScale;
                }
                if (RELU) { v0 = fmaxf(v0, 0.f); v1 = fmaxf(v1, 0.f); }
                if (BN) {
                    v0 = (v0 - mn2.x) * (g2.x * iv2.x) + be2.x;
                    v1 = (v1 - mn2.y) * (g2.y * iv2.y) + be2.y;
                }
                *(float2*)(C + (size_t)row * N + col) = make_float2(v0, v1);
            }
        }
    }
}

// ---------------------------------------------------------------------------
// Row softmax over the last axis of w[B, LDIM, LDIM] (in place).
// One block per row, 256 threads, one float4 per thread.
// ---------------------------------------------------------------------------
__global__ __launch_bounds__(256)
void softmax_row(float* __restrict__ w)
{
    __shared__ float s_max[8], s_sum[8];
    float* p = w + ((size_t)blockIdx.y * LDIM + blockIdx.x) * LDIM;
    const int t = threadIdx.x, wi = t >> 5, li = t & 31;

    float4 x = reinterpret_cast<const float4*>(p)[t];
    float mx = fmaxf(fmaxf(x.x, x.y), fmaxf(x.z, x.w));
    #pragma unroll
    for (int o = 16; o; o >>= 1) mx = fmaxf(mx, __shfl_xor_sync(~0u, mx, o));
    if (li == 0) s_max[wi] = mx;
    __syncthreads();
    if (t == 0) {
        float v = s_max[0];
        #pragma unroll
        for (int i = 1; i < 8; i++) v = fmaxf(v, s_max[i]);
        s_max[0] = v;
    }
    __syncthreads();
    mx = s_max[0];
    float e0 = __expf(x.x - mx), e1 = __expf(x.y - mx);
    float e2 = __expf(x.z - mx), e3 = __expf(x.w - mx);
    float s = e0 + e1 + e2 + e3;
    #pragma unroll
    for (int o = 16; o; o >>= 1) s += __shfl_xor_sync(~0u, s, o);
    if (li == 0) s_sum[wi] = s;
    __syncthreads();
    if (t == 0) {
        float v = 0.f;
        #pragma unroll
        for (int i = 0; i < 8; i++) v += s_sum[i];
        s_sum[0] = v;
    }
    __syncthreads();
    const float inv = 1.0f / s_sum[0];
    reinterpret_cast<float4*>(p)[t] = make_float4(e0 * inv, e1 * inv, e2 * inv, e3 * inv);
}

// ---------------------------------------------------------------------------
// Batched transpose: out[z][C][R] = in[z][R][C].  Block (32,8), tile 32x32.
// ---------------------------------------------------------------------------
__global__ __launch_bounds__(256)
void transpose32(const float* __restrict__ in, float* __restrict__ out, int R, int C)
{
    __shared__ float tile[32][33];
    const size_t zo = (size_t)blockIdx.z * (size_t)R * C;
    in += zo; out += zo;
    const int c0 = blockIdx.x * 32, r0 = blockIdx.y * 32;
    const int tx = threadIdx.x, ty = threadIdx.y;
    #pragma unroll
    for (int i = 0; i < 4; i++)
        tile[ty + 8 * i][tx] = in[(size_t)(r0 + ty + 8 * i) * C + c0 + tx];
    __syncthreads();
    #pragma unroll
    for (int i = 0; i < 4; i++)
        out[(size_t)(c0 + ty + 8 * i) * R + r0 + tx] = tile[tx][ty + 8 * i];
}

// ---------------------------------------------------------------------------
// Host-side launch helper
// ---------------------------------------------------------------------------
template<int MUL, bool BIAS, bool RELU, bool BN>
static void gemmNT(const float* A, size_t aB, const float* B, size_t bB,
                   float* C, size_t cB, int M, int N, int K, int Z,
                   const float* bias,
                   const float* mul, size_t mulB, float mulScale,
                   const float* gm, const float* bt,
                   const float* mn, const float* vr)
{
    cudaFuncSetAttribute(gemm_mma<MUL, BIAS, RELU, BN>,
                         cudaFuncAttributeMaxDynamicSharedMemorySize, GEMM_SMEM_BYTES);
    dim3 grid(N / 128, M / 128, Z);
    gemm_mma<MUL, BIAS, RELU, BN><<<grid, 256, GEMM_SMEM_BYTES>>>(
        A, aB, B, bB, C, cB, M, N, K, bias, mul, mulB, mulScale, gm, bt, mn, vr);
}

extern "C" void kernel_launch(void* const* d_in, const int* in_sizes, int n_in,
                              void* d_out, int out_size)
{
    const float* seq1  = (const float*)d_in[0];
    const float* seq2  = (const float*)d_in[1];
    const float* disto = (const float*)d_in[2];
    const float* kW1 = (const float*)d_in[3];  const float* kb1 = (const float*)d_in[4];
    const float* kW2 = (const float*)d_in[5];  const float* kb2 = (const float*)d_in[6];
    const float* qW1 = (const float*)d_in[7];  const float* qb1 = (const float*)d_in[8];
    const float* qW2 = (const float*)d_in[9];  const float* qb2 = (const float*)d_in[10];
    const float* vW1 = (const float*)d_in[11]; const float* vb1 = (const float*)d_in[12];
    const float* vW2 = (const float*)d_in[13]; const float* vb2 = (const float*)d_in[14];
    const float* fc1W = (const float*)d_in[15]; const float* fc1b = (const float*)d_in[16];
    const float* fc2W = (const float*)d_in[17]; const float* fc2b = (const float*)d_in[18];
    const float* gma  = (const float*)d_in[19]; const float* bta  = (const float*)d_in[20];
    const float* mean = (const float*)d_in[21]; const float* var  = (const float*)d_in[22];
    float* out = (float*)d_out;

    float *h, *k1, *q1, *v1, *k2, *q2, *v2, *w1, *w2, *ap1, *ap2, *v1T, *v2T, *dT, *wT;
    cudaGetSymbolAddress((void**)&h,   g_h);
    cudaGetSymbolAddress((void**)&k1,  g_k1);
    cudaGetSymbolAddress((void**)&q1,  g_q1);
    cudaGetSymbolAddress((void**)&v1,  g_v1);
    cudaGetSymbolAddress((void**)&k2,  g_k2);
    cudaGetSymbolAddress((void**)&q2,  g_q2);
    cudaGetSymbolAddress((void**)&v2,  g_v2);
    cudaGetSymbolAddress((void**)&w1,  g_w1);
    cudaGetSymbolAddress((void**)&w2,  g_w2);
    cudaGetSymbolAddress((void**)&ap1, g_ap1);
    cudaGetSymbolAddress((void**)&ap2, g_ap2);
    cudaGetSymbolAddress((void**)&v1T, g_v1T);
    cudaGetSymbolAddress((void**)&v2T, g_v2T);
    cudaGetSymbolAddress((void**)&dT,  g_dT);
    cudaGetSymbolAddress((void**)&wT,  g_wT);

    const size_t seqB = (size_t)LDIM * SDIM;
    const size_t matB = (size_t)LDIM * LDIM;
    const int MFLAT = BATCH * LDIM;   // 16384
    const float invS = 1.0f / 256.0f;

    // ---- transpose distogram (dT[b][m][l] = disto[b][l][m]) ----
    transpose32<<<dim3(32, 32, BATCH), dim3(32, 8)>>>(disto, dT, LDIM, LDIM);

    // ---- transpose the 8 weight matrices (WT[n][k] = W[k][n]) ----
    const float* Ws[8] = {kW1, kW2, qW1, qW2, vW1, vW2, fc1W, fc2W};
    for (int i = 0; i < 8; i++)
        transpose32<<<dim3(8, 8, 1), dim3(32, 8)>>>(Ws[i], wT + i * 65536, 256, 256);

    // ---- MLPs: out = (relu(seq@W1+b1))@W2+b2, batch flattened ----
    struct { const float* seq; int i1; const float* b1; int i2; const float* b2; float* dst; }
    mlps[6] = {
        {seq1, 0, kb1, 1, kb2, k1}, {seq1, 2, qb1, 3, qb2, q1}, {seq1, 4, vb1, 5, vb2, v1},
        {seq2, 0, kb1, 1, kb2, k2}, {seq2, 2, qb1, 3, qb2, q2}, {seq2, 4, vb1, 5, vb2, v2},
    };
    for (int i = 0; i < 6; i++) {
        gemmNT<0, true, true, false>(mlps[i].seq, 0, wT + mlps[i].i1 * 65536, 0, h, 0,
                                     MFLAT, SDIM, SDIM, 1, mlps[i].b1,
                                     nullptr, 0, 0.f, nullptr, nullptr, nullptr, nullptr);
        gemmNT<0, true, false, false>(h, 0, wT + mlps[i].i2 * 65536, 0, mlps[i].dst, 0,
                                      MFLAT, SDIM, SDIM, 1, mlps[i].b2,
                                      nullptr, 0, 0.f, nullptr, nullptr, nullptr, nullptr);
    }

    // ---- transpose V (v1T[b][s][l] = v1[b][l][s]) ----
    transpose32<<<dim3(8, 32, BATCH), dim3(32, 8)>>>(v1, v1T, LDIM, SDIM);
    transpose32<<<dim3(8, 32, BATCH), dim3(32, 8)>>>(v2, v2T, LDIM, SDIM);

    // ---- transposed scores ----
    // s1t[b][m][l] = (k2[b,m] . q1[b,l]) * dT[b][m][l] / 256
    gemmNT<1, false, false, false>(k2, seqB, q1, seqB, w1, matB, LDIM, LDIM, SDIM, BATCH,
                                   nullptr, dT, matB, invS, nullptr, nullptr, nullptr, nullptr);
    // s2t[b][l][m] = (k1[b,l] . q2[b,m]) * disto[b][l][m] / 256
    gemmNT<1, false, false, false>(k1, seqB, q2, seqB, w2, matB, LDIM, LDIM, SDIM, BATCH,
                                   nullptr, disto, matB, invS, nullptr, nullptr, nullptr, nullptr);

    // ---- softmax over the (contiguous) last axis of the transposed scores ----
    softmax_row<<<dim3(LDIM, BATCH), 256>>>(w1);
    softmax_row<<<dim3(LDIM, BATCH), 256>>>(w2);

    // ---- attention apply ----
    // ap1[b][m][s] = sum_l s1t[b][m][l] * v1T[b][s][l]
    gemmNT<0, false, false, false>(w1, matB, v1T, seqB, ap1, seqB, LDIM, SDIM, LDIM, BATCH,
                                   nullptr, nullptr, 0, 0.f, nullptr, nullptr, nullptr, nullptr);
    gemmNT<0, false, false, false>(w2, matB, v2T, seqB, ap2, seqB, LDIM, SDIM, LDIM, BATCH,
                                   nullptr, nullptr, 0, 0.f, nullptr, nullptr, nullptr, nullptr);

    // ---- output projections: bn(relu(ap @ fcW + fcb)) ----
    gemmNT<0, true, true, true>(ap1, 0, wT + 6 * 65536, 0, out, 0,
                                MFLAT, SDIM, SDIM, 1, fc1b,
                                nullptr, 0, 0.f, gma, bta, mean, var);
    gemmNT<0, true, true, true>(ap2, 0, wT + 7 * 65536, 0, out + (size_t)SEQ_ELEMS, 0,
                                MFLAT, SDIM, SDIM, 1, fc2b,
                                nullptr, 0, 0.f, gma, bta, mean, var);
}

// round 7
// speedup vs baseline: 2.2971x; 1.1663x over previous
#include <cuda_runtime.h>
#include <cstdint>
#include <math.h>

// ---------------------------------------------------------------------------
// Problem constants
// ---------------------------------------------------------------------------
#define BATCH 16
#define LDIM  1024
#define SDIM  256
#define EPS_BN 1e-3f

#define SEQ_ELEMS (BATCH * LDIM * SDIM)          // 4,194,304 floats
#define MAT_ELEMS ((size_t)BATCH * LDIM * LDIM)  // 16,777,216 floats
#define HID_ELEMS ((size_t)BATCH * LDIM * 768)   // 12,582,912 floats per seq

// Scratch (device globals: allocation-free, graph-capture safe)
__device__ float g_h   [2 * HID_ELEMS];          // layer-1 hidden, both seqs
__device__ float g_kqv1[3 * (size_t)SEQ_ELEMS];  // k1,q1,v1
__device__ float g_kqv2[3 * (size_t)SEQ_ELEMS];  // k2,q2,v2
__device__ float g_w1 [MAT_ELEMS];               // s1t -> softmaxed
__device__ float g_w2 [MAT_ELEMS];               // s2t
__device__ float g_ap1[SEQ_ELEMS];
__device__ float g_ap2[SEQ_ELEMS];
__device__ float g_v1T[SEQ_ELEMS];
__device__ float g_v2T[SEQ_ELEMS];
__device__ float g_dT [MAT_ELEMS];               // distogram transposed
__device__ float g_wT [8 * 256 * 256];           // transposed weights: kW1,qW1,vW1,kW2,qW2,vW2,fc1W,fc2W
__device__ float g_bc [2 * 768];                 // concat biases: [kb1|qb1|vb1], [kb2|qb2|vb2]

// ---------------------------------------------------------------------------
// tf32 round-to-nearest of fp32 (kept in 32-bit container)
// ---------------------------------------------------------------------------
__device__ __forceinline__ float tf32r(float x) {
    uint32_t u;
    asm("cvt.rna.tf32.f32 %0, %1;" : "=r"(u) : "f"(x));
    return __uint_as_float(u);
}

// ---------------------------------------------------------------------------
// Warp-level tf32 MMA GEMM: C[z][M,N] = epilogue( A[z][M,K] @ B[z][N,K]^T )
// CTA tile 128x128, K-chunk 32, 8 warps (2Mx4N), m16n8k8 tf32, fp32 accum.
// lda = row stride of A (supports column-sliced A); B and C rows are tight.
// __launch_bounds__(256,2): cap 128 regs -> 2 CTAs/SM.
// ---------------------------------------------------------------------------
#define GEMM_SMEM_BYTES (8704 * 8)   // 4 buffers (A0,B0,A1,B1) x 2176 float2

template<int MUL, bool BIAS, bool RELU, bool BN>
__global__ __launch_bounds__(256, 2)
void gemm_mma(const float* __restrict__ A, size_t aB, int lda,
              const float* __restrict__ B, size_t bB,
              float* __restrict__ C, size_t cB,
              int M, int N, int K,
              const float* __restrict__ bias, size_t biasB,
              const float* __restrict__ mul, size_t mulB, float mulScale,
              const float* __restrict__ gm, const float* __restrict__ bt,
              const float* __restrict__ mn, const float* __restrict__ vr)
{
    extern __shared__ float2 sm[];
    const int tid  = threadIdx.x;
    const int lane = tid & 31;
    const int wid  = tid >> 5;
    const int wm   = wid >> 2;            // 0..1  (64-row slab)
    const int wn   = wid & 3;             // 0..3  (32-col slab)
    const int z    = blockIdx.z;
    const int m0   = blockIdx.y * 128;
    const int n0   = blockIdx.x * 128;

    A += (size_t)z * aB + (size_t)m0 * lda;
    B += (size_t)z * bB + (size_t)n0 * K;
    C += (size_t)z * cB;
    if (BIAS) bias += (size_t)z * biasB;
    if (MUL)  mul  += (size_t)z * mulB;

    float2* Abuf[2] = { sm,            sm + 4352 };
    float2* Bbuf[2] = { sm + 2176,     sm + 6528 };

    // ---- store-phase constants ----
    const int jj   = tid & 7;             // float4 index within a 32-k row
    const int r_lo = tid >> 3;            // 0..31 (row within 32-row block)
    const int s_st = jj >> 1;
    const int h_st = jj & 1;
    const int slotbase = ((s_st ^ (r_lo & 3)) << 2);

    float acc[4][4][4];
    #pragma unroll
    for (int i = 0; i < 4; i++)
        #pragma unroll
        for (int j = 0; j < 4; j++)
            #pragma unroll
            for (int t = 0; t < 4; t++) acc[i][j][t] = 0.f;

    const int nch = K >> 5;
    float4 va[4], vb[4];

    #define LD_CHUNK(ck) do { \
        const float* Ak = A + (ck) * 32 + jj * 4; \
        const float* Bk = B + (ck) * 32 + jj * 4; \
        _Pragma("unroll") \
        for (int it = 0; it < 4; ++it) { \
            va[it] = *(const float4*)(Ak + (size_t)(it * 32 + r_lo) * lda); \
            vb[it] = *(const float4*)(Bk + (size_t)(it * 32 + r_lo) * K); \
        } \
    } while (0)

    #define STS_CHUNK(bp) do { \
        float* Af = (float*)(Abuf[bp]); \
        float* Bf = (float*)(Bbuf[bp]); \
        _Pragma("unroll") \
        for (int it = 0; it < 4; ++it) { \
            const int base = ((it * 32 + r_lo) * 17 + slotbase) * 2 + h_st; \
            Af[base + 0] = tf32r(va[it].x); Af[base + 2] = tf32r(va[it].y); \
            Af[base + 4] = tf32r(va[it].z); Af[base + 6] = tf32r(va[it].w); \
            Bf[base + 0] = tf32r(vb[it].x); Bf[base + 2] = tf32r(vb[it].y); \
            Bf[base + 4] = tf32r(vb[it].z); Bf[base + 6] = tf32r(vb[it].w); \
        } \
    } while (0)

    const int g  = lane >> 2;
    const int cc = lane & 3;

    LD_CHUNK(0);
    STS_CHUNK(0);
    __syncthreads();

    for (int ch = 0; ch < nch; ++ch) {
        if (ch + 1 < nch) LD_CHUNK(ch + 1);

        const float2* Ab = Abuf[ch & 1];
        const float2* Bb = Bbuf[ch & 1];
        #pragma unroll
        for (int s = 0; s < 4; ++s) {
            float2 af[4][2], bf[4];
            #pragma unroll
            for (int i = 0; i < 4; ++i) {
                const int rA = wm * 64 + i * 16 + g;
                const int sl = ((s ^ (rA & 3)) << 2) + cc;
                af[i][0] = Ab[rA * 17 + sl];
                af[i][1] = Ab[(rA + 8) * 17 + sl];
            }
            #pragma unroll
            for (int j = 0; j < 4; ++j) {
                const int rB = wn * 32 + j * 8 + g;
                const int sl = ((s ^ (rB & 3)) << 2) + cc;
                bf[j] = Bb[rB * 17 + sl];
            }
            #pragma unroll
            for (int i = 0; i < 4; ++i)
                #pragma unroll
                for (int j = 0; j < 4; ++j) {
                    asm volatile(
                        "mma.sync.aligned.m16n8k8.row.col.f32.tf32.tf32.f32 "
                        "{%0,%1,%2,%3}, {%4,%5,%6,%7}, {%8,%9}, {%0,%1,%2,%3};"
                        : "+f"(acc[i][j][0]), "+f"(acc[i][j][1]),
                          "+f"(acc[i][j][2]), "+f"(acc[i][j][3])
                        : "r"(__float_as_uint(af[i][0].x)), "r"(__float_as_uint(af[i][1].x)),
                          "r"(__float_as_uint(af[i][0].y)), "r"(__float_as_uint(af[i][1].y)),
                          "r"(__float_as_uint(bf[j].x)),    "r"(__float_as_uint(bf[j].y)));
                }
        }

        if (ch + 1 < nch) STS_CHUNK((ch + 1) & 1);
        __syncthreads();
    }
    #undef LD_CHUNK
    #undef STS_CHUNK

    // ---- epilogue ----
    #pragma unroll
    for (int j = 0; j < 4; ++j) {
        const int col = n0 + wn * 32 + j * 8 + cc * 2;
        float2 b2, g2, be2, mn2, iv2;
        if (BIAS) b2 = *(const float2*)(bias + col);
        if (BN) {
            g2  = *(const float2*)(gm + col);
            be2 = *(const float2*)(bt + col);
            mn2 = *(const float2*)(mn + col);
            float2 v2 = *(const float2*)(vr + col);
            iv2 = make_float2(rsqrtf(v2.x + EPS_BN), rsqrtf(v2.y + EPS_BN));
        }
        #pragma unroll
        for (int i = 0; i < 4; ++i) {
            const int row0 = m0 + wm * 64 + i * 16 + g;
            #pragma unroll
            for (int hh = 0; hh < 2; ++hh) {
                const int row = row0 + hh * 8;
                float v0 = acc[i][j][hh * 2 + 0];
                float v1 = acc[i][j][hh * 2 + 1];
                if (BIAS) { v0 += b2.x; v1 += b2.y; }
                if (MUL) {
                    float2 m2 = *(const float2*)(mul + (size_t)row * N + col);
                    v0 *= m2.x * mulScale; v1 *= m2.y * mulScale;
                }
                if (RELU) { v0 = fmaxf(v0, 0.f); v1 = fmaxf(v1, 0.f); }
                if (BN) {
                    v0 = (v0 - mn2.x) * (g2.x * iv2.x) + be2.x;
                    v1 = (v1 - mn2.y) * (g2.y * iv2.y) + be2.y;
                }
                *(float2*)(C + (size_t)row * N + col) = make_float2(v0, v1);
            }
        }
    }
}

// ---------------------------------------------------------------------------
// Row softmax over the last axis of w[B, LDIM, LDIM] (in place).
// ---------------------------------------------------------------------------
__global__ __launch_bounds__(256)
void softmax_row(float* __restrict__ w)
{
    __shared__ float s_max[8], s_sum[8];
    float* p = w + ((size_t)blockIdx.y * LDIM + blockIdx.x) * LDIM;
    const int t = threadIdx.x, wi = t >> 5, li = t & 31;

    float4 x = reinterpret_cast<const float4*>(p)[t];
    float mx = fmaxf(fmaxf(x.x, x.y), fmaxf(x.z, x.w));
    #pragma unroll
    for (int o = 16; o; o >>= 1) mx = fmaxf(mx, __shfl_xor_sync(~0u, mx, o));
    if (li == 0) s_max[wi] = mx;
    __syncthreads();
    if (t == 0) {
        float v = s_max[0];
        #pragma unroll
        for (int i = 1; i < 8; i++) v = fmaxf(v, s_max[i]);
        s_max[0] = v;
    }
    __syncthreads();
    mx = s_max[0];
    float e0 = __expf(x.x - mx), e1 = __expf(x.y - mx);
    float e2 = __expf(x.z - mx), e3 = __expf(x.w - mx);
    float s = e0 + e1 + e2 + e3;
    #pragma unroll
    for (int o = 16; o; o >>= 1) s += __shfl_xor_sync(~0u, s, o);
    if (li == 0) s_sum[wi] = s;
    __syncthreads();
    if (t == 0) {
        float v = 0.f;
        #pragma unroll
        for (int i = 0; i < 8; i++) v += s_sum[i];
        s_sum[0] = v;
    }
    __syncthreads();
    const float inv = 1.0f / s_sum[0];
    reinterpret_cast<float4*>(p)[t] = make_float4(e0 * inv, e1 * inv, e2 * inv, e3 * inv);
}

// ---------------------------------------------------------------------------
// Batched transpose: out[z][C][R] = in[z][R][C].  Block (32,8), tile 32x32.
// ---------------------------------------------------------------------------
__global__ __launch_bounds__(256)
void transpose32(const float* __restrict__ in, float* __restrict__ out, int R, int C)
{
    __shared__ float tile[32][33];
    const size_t zo = (size_t)blockIdx.z * (size_t)R * C;
    in += zo; out += zo;
    const int c0 = blockIdx.x * 32, r0 = blockIdx.y * 32;
    const int tx = threadIdx.x, ty = threadIdx.y;
    #pragma unroll
    for (int i = 0; i < 4; i++)
        tile[ty + 8 * i][tx] = in[(size_t)(r0 + ty + 8 * i) * C + c0 + tx];
    __syncthreads();
    #pragma unroll
    for (int i = 0; i < 4; i++)
        out[(size_t)(c0 + ty + 8 * i) * R + r0 + tx] = tile[tx][ty + 8 * i];
}

// ---------------------------------------------------------------------------
// Concatenate the 6 MLP bias vectors into g_bc: [kb1|qb1|vb1], [kb2|qb2|vb2]
// ---------------------------------------------------------------------------
__global__ void bias_concat(float* __restrict__ bc,
                            const float* kb1, const float* qb1, const float* vb1,
                            const float* kb2, const float* qb2, const float* vb2)
{
    const int i = threadIdx.x;   // 0..255
    bc[i]        = kb1[i]; bc[256 + i]  = qb1[i]; bc[512 + i]  = vb1[i];
    bc[768 + i]  = kb2[i]; bc[1024 + i] = qb2[i]; bc[1280 + i] = vb2[i];
}

// ---------------------------------------------------------------------------
// Host-side launch helper
// ---------------------------------------------------------------------------
template<int MUL, bool BIAS, bool RELU, bool BN>
static void gemmNT(const float* A, size_t aB, int lda,
                   const float* B, size_t bB,
                   float* C, size_t cB, int M, int N, int K, int Z,
                   const float* bias, size_t biasB,
                   const float* mul, size_t mulB, float mulScale,
                   const float* gm, const float* bt,
                   const float* mn, const float* vr)
{
    cudaFuncSetAttribute(gemm_mma<MUL, BIAS, RELU, BN>,
                         cudaFuncAttributeMaxDynamicSharedMemorySize, GEMM_SMEM_BYTES);
    dim3 grid(N / 128, M / 128, Z);
    gemm_mma<MUL, BIAS, RELU, BN><<<grid, 256, GEMM_SMEM_BYTES>>>(
        A, aB, lda, B, bB, C, cB, M, N, K, bias, biasB, mul, mulB, mulScale, gm, bt, mn, vr);
}

extern "C" void kernel_launch(void* const* d_in, const int* in_sizes, int n_in,
                              void* d_out, int out_size)
{
    const float* seq1  = (const float*)d_in[0];
    const float* seq2  = (const float*)d_in[1];
    const float* disto = (const float*)d_in[2];
    const float* kW1 = (const float*)d_in[3];  const float* kb1 = (const float*)d_in[4];
    const float* kW2 = (const float*)d_in[5];  const float* kb2 = (const float*)d_in[6];
    const float* qW1 = (const float*)d_in[7];  const float* qb1 = (const float*)d_in[8];
    const float* qW2 = (const float*)d_in[9];  const float* qb2 = (const float*)d_in[10];
    const float* vW1 = (const float*)d_in[11]; const float* vb1 = (const float*)d_in[12];
    const float* vW2 = (const float*)d_in[13]; const float* vb2 = (const float*)d_in[14];
    const float* fc1W = (const float*)d_in[15]; const float* fc1b = (const float*)d_in[16];
    const float* fc2W = (const float*)d_in[17]; const float* fc2b = (const float*)d_in[18];
    const float* gma  = (const float*)d_in[19]; const float* bta  = (const float*)d_in[20];
    const float* mean = (const float*)d_in[21]; const float* var  = (const float*)d_in[22];
    float* out = (float*)d_out;

    float *h, *kqv1, *kqv2, *w1, *w2, *ap1, *ap2, *v1T, *v2T, *dT, *wT, *bc;
    cudaGetSymbolAddress((void**)&h,    g_h);
    cudaGetSymbolAddress((void**)&kqv1, g_kqv1);
    cudaGetSymbolAddress((void**)&kqv2, g_kqv2);
    cudaGetSymbolAddress((void**)&w1,   g_w1);
    cudaGetSymbolAddress((void**)&w2,   g_w2);
    cudaGetSymbolAddress((void**)&ap1,  g_ap1);
    cudaGetSymbolAddress((void**)&ap2,  g_ap2);
    cudaGetSymbolAddress((void**)&v1T,  g_v1T);
    cudaGetSymbolAddress((void**)&v2T,  g_v2T);
    cudaGetSymbolAddress((void**)&dT,   g_dT);
    cudaGetSymbolAddress((void**)&wT,   g_wT);
    cudaGetSymbolAddress((void**)&bc,   g_bc);

    const size_t seqB = (size_t)LDIM * SDIM;
    const size_t matB = (size_t)LDIM * LDIM;
    const int MFLAT = BATCH * LDIM;   // 16384
    const float invS = 1.0f / 256.0f;

    float* h1 = h;
    float* h2 = h + HID_ELEMS;
    const float* k1 = kqv1;  const float* q1 = kqv1 + SEQ_ELEMS;  float* v1 = kqv1 + 2 * (size_t)SEQ_ELEMS;
    const float* k2 = kqv2;  const float* q2 = kqv2 + SEQ_ELEMS;  float* v2 = kqv2 + 2 * (size_t)SEQ_ELEMS;

    // Launch order arranged so ncu (-s 5 -c 1) profiles launch #6 = big MLP GEMM.
    // (1) bias concat
    bias_concat<<<1, 256>>>(bc, kb1, qb1, vb1, kb2, qb2, vb2);
    // (2-5) weight transposes: kW1, qW1, vW1, kW2
    transpose32<<<dim3(8, 8, 1), dim3(32, 8)>>>(kW1, wT + 0 * 65536, 256, 256);
    transpose32<<<dim3(8, 8, 1), dim3(32, 8)>>>(qW1, wT + 1 * 65536, 256, 256);
    transpose32<<<dim3(8, 8, 1), dim3(32, 8)>>>(vW1, wT + 2 * 65536, 256, 256);
    transpose32<<<dim3(8, 8, 1), dim3(32, 8)>>>(kW2, wT + 3 * 65536, 256, 256);
    // (6) MLP layer 1, seq1: h1 = relu(seq1 @ [kW1|qW1|vW1] + bc1)   [16384 x 768]
    gemmNT<0, true, true, false>(seq1, 0, 256, wT, 0, h1, 0, MFLAT, 768, 256, 1,
                                 bc, 0, nullptr, 0, 0.f, nullptr, nullptr, nullptr, nullptr);
    // (7-8) remaining layer-2 weight transposes
    transpose32<<<dim3(8, 8, 1), dim3(32, 8)>>>(qW2, wT + 4 * 65536, 256, 256);
    transpose32<<<dim3(8, 8, 1), dim3(32, 8)>>>(vW2, wT + 5 * 65536, 256, 256);
    // (9) MLP layer 1, seq2
    gemmNT<0, true, true, false>(seq2, 0, 256, wT, 0, h2, 0, MFLAT, 768, 256, 1,
                                 bc, 0, nullptr, 0, 0.f, nullptr, nullptr, nullptr, nullptr);
    // (10-11) MLP layer 2, grid.z = 3 (k, q, v): A = h columns z*256..z*256+255 (lda=768)
    gemmNT<0, true, false, false>(h1, 256, 768, wT + 3 * 65536, 65536, kqv1, SEQ_ELEMS,
                                  MFLAT, 256, 256, 3, bc + 768, 256,
                                  nullptr, 0, 0.f, nullptr, nullptr, nullptr, nullptr);
    gemmNT<0, true, false, false>(h2, 256, 768, wT + 3 * 65536, 65536, kqv2, SEQ_ELEMS,
                                  MFLAT, 256, 256, 3, bc + 768, 256,
                                  nullptr, 0, 0.f, nullptr, nullptr, nullptr, nullptr);
    // (12-14) disto + fc weight transposes
    transpose32<<<dim3(32, 32, BATCH), dim3(32, 8)>>>(disto, dT, LDIM, LDIM);
    transpose32<<<dim3(8, 8, 1), dim3(32, 8)>>>(fc1W, wT + 6 * 65536, 256, 256);
    transpose32<<<dim3(8, 8, 1), dim3(32, 8)>>>(fc2W, wT + 7 * 65536, 256, 256);
    // (15-16) V transposes
    transpose32<<<dim3(8, 32, BATCH), dim3(32, 8)>>>(v1, v1T, LDIM, SDIM);
    transpose32<<<dim3(8, 32, BATCH), dim3(32, 8)>>>(v2, v2T, LDIM, SDIM);
    // (17) s1t[b][m][l] = (k2[b,m] . q1[b,l]) * dT[b][m][l] / 256
    gemmNT<1, false, false, false>(k2, seqB, 256, q1, seqB, w1, matB, LDIM, LDIM, SDIM, BATCH,
                                   nullptr, 0, dT, matB, invS, nullptr, nullptr, nullptr, nullptr);
    // (18) s2t[b][l][m] = (k1[b,l] . q2[b,m]) * disto[b][l][m] / 256
    gemmNT<1, false, false, false>(k1, seqB, 256, q2, seqB, w2, matB, LDIM, LDIM, SDIM, BATCH,
                                   nullptr, 0, disto, matB, invS, nullptr, nullptr, nullptr, nullptr);
    // (19-20) softmax over the contiguous last axis
    softmax_row<<<dim3(LDIM, BATCH), 256>>>(w1);
    softmax_row<<<dim3(LDIM, BATCH), 256>>>(w2);
    // (21-22) attention apply: ap1[b][m][s] = sum_l s1t[b][m][l] * v1T[b][s][l]
    gemmNT<0, false, false, false>(w1, matB, LDIM, v1T, seqB, ap1, seqB, LDIM, SDIM, LDIM, BATCH,
                                   nullptr, 0, nullptr, 0, 0.f, nullptr, nullptr, nullptr, nullptr);
    gemmNT<0, false, false, false>(w2, matB, LDIM, v2T, seqB, ap2, seqB, LDIM, SDIM, LDIM, BATCH,
                                   nullptr, 0, nullptr, 0, 0.f, nullptr, nullptr, nullptr, nullptr);
    // (23-24) output projections: bn(relu(ap @ fcW + fcb))
    gemmNT<0, true, true, true>(ap1, 0, 256, wT + 6 * 65536, 0, out, 0, MFLAT, 256, 256, 1,
                                fc1b, 0, nullptr, 0, 0.f, gma, bta, mean, var);
    gemmNT<0, true, true, true>(ap2, 0, 256, wT + 7 * 65536, 0, out + (size_t)SEQ_ELEMS, 0,
                                MFLAT, 256, 256, 1, fc2b, 0, nullptr, 0, 0.f, gma, bta, mean, var);
}

// round 8
// speedup vs baseline: 3.5366x; 1.5396x over previous
#include <cuda_runtime.h>
#include <cstdint>
#include <math.h>

// ---------------------------------------------------------------------------
// Problem constants
// ---------------------------------------------------------------------------
#define BATCH 16
#define LDIM  1024
#define SDIM  256
#define EPS_BN 1e-3f

#define SEQ_ELEMS (BATCH * LDIM * SDIM)          // 4,194,304 floats
#define MAT_ELEMS ((size_t)BATCH * LDIM * LDIM)  // 16,777,216 floats
#define HID_ELEMS ((size_t)BATCH * LDIM * 768)

// Scratch (device globals: allocation-free, graph-capture safe)
__device__ float g_h   [2 * HID_ELEMS];
__device__ float g_kqv1[3 * (size_t)SEQ_ELEMS];  // k1,q1,v1 (tf32-rounded)
__device__ float g_kqv2[3 * (size_t)SEQ_ELEMS];  // k2,q2,v2
__device__ float g_w1 [MAT_ELEMS];               // s1t -> softmaxed (rounded)
__device__ float g_w2 [MAT_ELEMS];
__device__ float g_ap1[SEQ_ELEMS];
__device__ float g_ap2[SEQ_ELEMS];
__device__ float g_v1T[SEQ_ELEMS];
__device__ float g_v2T[SEQ_ELEMS];
__device__ float g_dT [MAT_ELEMS];               // distogram transposed (EXACT)
__device__ float g_wT [8 * 256 * 256];           // transposed weights (rounded)
__device__ float g_bc [2 * 768];
__device__ float g_sr1[SEQ_ELEMS];               // tf32-rounded seq1
__device__ float g_sr2[SEQ_ELEMS];               // tf32-rounded seq2

// ---------------------------------------------------------------------------
// tf32 round-to-nearest of fp32 (kept in 32-bit container)
// ---------------------------------------------------------------------------
__device__ __forceinline__ float tf32r(float x) {
    uint32_t u;
    asm("cvt.rna.tf32.f32 %0, %1;" : "=r"(u) : "f"(x));
    return __uint_as_float(u);
}

__device__ __forceinline__ uint32_t smem_u32(const void* p) {
    return (uint32_t)__cvta_generic_to_shared(p);
}

#define CP_ASYNC16(dst_u32, src_ptr) \
    asm volatile("cp.async.ca.shared.global [%0], [%1], 16;" \
                 :: "r"(dst_u32), "l"(src_ptr) : "memory")
#define CP_COMMIT() asm volatile("cp.async.commit_group;" ::: "memory")
#define CP_WAIT(n)  asm volatile("cp.async.wait_group %0;" :: "n"(n) : "memory")

// ---------------------------------------------------------------------------
// cp.async-pipelined tf32 MMA GEMM: C[z][M,N] = epi( A[z][M,K] @ B[z][N,K]^T )
// CTA 128x128, K-chunk 32, 3-stage cp.async pipeline, 8 warps (2Mx4N),
// m16n8k8 tf32. OPERANDS MUST BE PRE-ROUNDED TO TF32 by their producers.
// Smem per stage per operand: 128 rows x 32 floats, quad-swizzled:
//   quad qi (16B) of row r stored at quad index (qi ^ (r&7)).
// Epilogue: +bias -> *mul*mulScale -> relu -> batchnorm -> (opt) tf32 round.
// ---------------------------------------------------------------------------
#define NSTAGE 3
#define STG_FLOATS (128 * 32)                   // per operand per stage
#define GEMM_SMEM_BYTES (NSTAGE * 2 * STG_FLOATS * 4)   // 96 KB

template<int MUL, bool BIAS, bool RELU, bool BN, bool RNDC>
__global__ __launch_bounds__(256, 2)
void gemm_mma(const float* __restrict__ A, size_t aB, int lda,
              const float* __restrict__ B, size_t bB,
              float* __restrict__ C, size_t cB,
              int M, int N, int K,
              const float* __restrict__ bias, size_t biasB,
              const float* __restrict__ mul, size_t mulB, float mulScale,
              const float* __restrict__ gm, const float* __restrict__ bt,
              const float* __restrict__ mn, const float* __restrict__ vr)
{
    extern __shared__ float smem[];
    const int tid  = threadIdx.x;
    const int lane = tid & 31;
    const int wid  = tid >> 5;
    const int wm   = wid >> 2;            // 0..1
    const int wn   = wid & 3;             // 0..3
    const int z    = blockIdx.z;
    const int m0   = blockIdx.y * 128;
    const int n0   = blockIdx.x * 128;

    A += (size_t)z * aB + (size_t)m0 * lda;
    B += (size_t)z * bB + (size_t)n0 * K;
    C += (size_t)z * cB;
    if (BIAS) bias += (size_t)z * biasB;
    if (MUL)  mul  += (size_t)z * mulB;

    const uint32_t sbase = smem_u32(smem);
    // issue-phase per-thread quad coordinates: 4 quads per operand per stage
    const int r_ld  = tid >> 1;                  // rows: tid/2 and tid/2+... use qq scheme
    (void)r_ld;

    float acc[4][4][4];
    #pragma unroll
    for (int i = 0; i < 4; i++)
        #pragma unroll
        for (int j = 0; j < 4; j++)
            #pragma unroll
            for (int t = 0; t < 4; t++) acc[i][j][t] = 0.f;

    const int nch = K >> 5;

    // ---- issue one chunk's cp.asyncs into stage p ----
    #define ISSUE(ck, p) do { \
        const uint32_t Ad = sbase + (uint32_t)(p) * (2 * STG_FLOATS * 4); \
        const uint32_t Bd = Ad + STG_FLOATS * 4; \
        const float* Ak = A + (ck) * 32; \
        const float* Bk = B + (ck) * 32; \
        _Pragma("unroll") \
        for (int it = 0; it < 4; ++it) { \
            const int qq = it * 256 + tid;       /* 0..1023 */ \
            const int r  = qq >> 3, qi = qq & 7; \
            const uint32_t off = (uint32_t)(r * 32 + ((qi ^ (r & 7)) << 2)) * 4; \
            CP_ASYNC16(Ad + off, Ak + (size_t)r * lda + qi * 4); \
            CP_ASYNC16(Bd + off, Bk + (size_t)r * K   + qi * 4); \
        } \
        CP_COMMIT(); \
    } while (0)

    const int g  = lane >> 2;
    const int cc = lane & 3;

    ISSUE(0, 0);
    ISSUE(1, 1);

    for (int ch = 0; ch < nch; ++ch) {
        CP_WAIT(1);                // stage ch resident (ch+1 may be in flight)
        __syncthreads();
        if (ch + 2 < nch) ISSUE(ch + 2, (ch + 2) % NSTAGE);

        const float* Ab = smem + (ch % NSTAGE) * (2 * STG_FLOATS);
        const float* Bb = Ab + STG_FLOATS;

        #pragma unroll
        for (int s = 0; s < 4; ++s) {
            float a0[4], a1[4], a2[4], a3[4], b0[4], b1[4];
            #pragma unroll
            for (int i = 0; i < 4; ++i) {
                const int rA = wm * 64 + i * 16 + g;
                const int rA2 = rA + 8;
                a0[i] = Ab[rA  * 32 + (((2*s)     ^ (rA  & 7)) << 2) + cc];
                a2[i] = Ab[rA  * 32 + (((2*s + 1) ^ (rA  & 7)) << 2) + cc];
                a1[i] = Ab[rA2 * 32 + (((2*s)     ^ (rA2 & 7)) << 2) + cc];
                a3[i] = Ab[rA2 * 32 + (((2*s + 1) ^ (rA2 & 7)) << 2) + cc];
            }
            #pragma unroll
            for (int j = 0; j < 4; ++j) {
                const int rB = wn * 32 + j * 8 + g;
                b0[j] = Bb[rB * 32 + (((2*s)     ^ (rB & 7)) << 2) + cc];
                b1[j] = Bb[rB * 32 + (((2*s + 1) ^ (rB & 7)) << 2) + cc];
            }
            #pragma unroll
            for (int i = 0; i < 4; ++i)
                #pragma unroll
                for (int j = 0; j < 4; ++j) {
                    asm volatile(
                        "mma.sync.aligned.m16n8k8.row.col.f32.tf32.tf32.f32 "
                        "{%0,%1,%2,%3}, {%4,%5,%6,%7}, {%8,%9}, {%0,%1,%2,%3};"
                        : "+f"(acc[i][j][0]), "+f"(acc[i][j][1]),
                          "+f"(acc[i][j][2]), "+f"(acc[i][j][3])
                        : "r"(__float_as_uint(a0[i])), "r"(__float_as_uint(a1[i])),
                          "r"(__float_as_uint(a2[i])), "r"(__float_as_uint(a3[i])),
                          "r"(__float_as_uint(b0[j])), "r"(__float_as_uint(b1[j])));
                }
        }
        __syncthreads();
    }
    #undef ISSUE

    // ---- epilogue ----
    #pragma unroll
    for (int j = 0; j < 4; ++j) {
        const int col = n0 + wn * 32 + j * 8 + cc * 2;
        float2 b2, g2, be2, mn2, iv2;
        if (BIAS) b2 = *(const float2*)(bias + col);
        if (BN) {
            g2  = *(const float2*)(gm + col);
            be2 = *(const float2*)(bt + col);
            mn2 = *(const float2*)(mn + col);
            float2 v2 = *(const float2*)(vr + col);
            iv2 = make_float2(rsqrtf(v2.x + EPS_BN), rsqrtf(v2.y + EPS_BN));
        }
        #pragma unroll
        for (int i = 0; i < 4; ++i) {
            const int row0 = m0 + wm * 64 + i * 16 + g;
            #pragma unroll
            for (int hh = 0; hh < 2; ++hh) {
                const int row = row0 + hh * 8;
                float v0 = acc[i][j][hh * 2 + 0];
                float v1 = acc[i][j][hh * 2 + 1];
                if (BIAS) { v0 += b2.x; v1 += b2.y; }
                if (MUL) {
                    float2 m2 = *(const float2*)(mul + (size_t)row * N + col);
                    v0 *= m2.x * mulScale; v1 *= m2.y * mulScale;
                }
                if (RELU) { v0 = fmaxf(v0, 0.f); v1 = fmaxf(v1, 0.f); }
                if (BN) {
                    v0 = (v0 - mn2.x) * (g2.x * iv2.x) + be2.x;
                    v1 = (v1 - mn2.y) * (g2.y * iv2.y) + be2.y;
                }
                if (RNDC) { v0 = tf32r(v0); v1 = tf32r(v1); }
                *(float2*)(C + (size_t)row * N + col) = make_float2(v0, v1);
            }
        }
    }
}

// ---------------------------------------------------------------------------
// Row softmax over the last axis (in place); output tf32-rounded (feeds MMA).
// ---------------------------------------------------------------------------
__global__ __launch_bounds__(256)
void softmax_row(float* __restrict__ w)
{
    __shared__ float s_max[8], s_sum[8];
    float* p = w + ((size_t)blockIdx.y * LDIM + blockIdx.x) * LDIM;
    const int t = threadIdx.x, wi = t >> 5, li = t & 31;

    float4 x = reinterpret_cast<const float4*>(p)[t];
    float mx = fmaxf(fmaxf(x.x, x.y), fmaxf(x.z, x.w));
    #pragma unroll
    for (int o = 16; o; o >>= 1) mx = fmaxf(mx, __shfl_xor_sync(~0u, mx, o));
    if (li == 0) s_max[wi] = mx;
    __syncthreads();
    if (t == 0) {
        float v = s_max[0];
        #pragma unroll
        for (int i = 1; i < 8; i++) v = fmaxf(v, s_max[i]);
        s_max[0] = v;
    }
    __syncthreads();
    mx = s_max[0];
    float e0 = __expf(x.x - mx), e1 = __expf(x.y - mx);
    float e2 = __expf(x.z - mx), e3 = __expf(x.w - mx);
    float s = e0 + e1 + e2 + e3;
    #pragma unroll
    for (int o = 16; o; o >>= 1) s += __shfl_xor_sync(~0u, s, o);
    if (li == 0) s_sum[wi] = s;
    __syncthreads();
    if (t == 0) {
        float v = 0.f;
        #pragma unroll
        for (int i = 0; i < 8; i++) v += s_sum[i];
        s_sum[0] = v;
    }
    __syncthreads();
    const float inv = 1.0f / s_sum[0];
    reinterpret_cast<float4*>(p)[t] =
        make_float4(tf32r(e0 * inv), tf32r(e1 * inv), tf32r(e2 * inv), tf32r(e3 * inv));
}

// ---------------------------------------------------------------------------
// Batched transpose: out[z][C][R] = in[z][R][C]. RND: tf32-round output.
// ---------------------------------------------------------------------------
template<bool RND>
__global__ __launch_bounds__(256)
void transpose32(const float* __restrict__ in, float* __restrict__ out, int R, int C)
{
    __shared__ float tile[32][33];
    const size_t zo = (size_t)blockIdx.z * (size_t)R * C;
    in += zo; out += zo;
    const int c0 = blockIdx.x * 32, r0 = blockIdx.y * 32;
    const int tx = threadIdx.x, ty = threadIdx.y;
    #pragma unroll
    for (int i = 0; i < 4; i++)
        tile[ty + 8 * i][tx] = in[(size_t)(r0 + ty + 8 * i) * C + c0 + tx];
    __syncthreads();
    #pragma unroll
    for (int i = 0; i < 4; i++) {
        float v = tile[tx][ty + 8 * i];
        out[(size_t)(c0 + ty + 8 * i) * R + r0 + tx] = RND ? tf32r(v) : v;
    }
}

// ---------------------------------------------------------------------------
// Transpose all 8 weight matrices (256x256) in one launch; tf32-rounded.
// ---------------------------------------------------------------------------
__global__ __launch_bounds__(256)
void wtrans8(const float* w0, const float* w1, const float* w2, const float* w3,
             const float* w4, const float* w5, const float* w6, const float* w7,
             float* __restrict__ out)
{
    __shared__ float tile[32][33];
    const float* srcs[8] = {w0, w1, w2, w3, w4, w5, w6, w7};
    const float* in = srcs[blockIdx.z];
    float* o = out + (size_t)blockIdx.z * 65536;
    const int c0 = blockIdx.x * 32, r0 = blockIdx.y * 32;
    const int tx = threadIdx.x, ty = threadIdx.y;
    #pragma unroll
    for (int i = 0; i < 4; i++)
        tile[ty + 8 * i][tx] = in[(size_t)(r0 + ty + 8 * i) * 256 + c0 + tx];
    __syncthreads();
    #pragma unroll
    for (int i = 0; i < 4; i++)
        o[(size_t)(c0 + ty + 8 * i) * 256 + r0 + tx] = tf32r(tile[tx][ty + 8 * i]);
}

// ---------------------------------------------------------------------------
// tf32-round both seq tensors (grid-stride float4)
// ---------------------------------------------------------------------------
__global__ __launch_bounds__(256)
void round_seqs(const float4* __restrict__ a, float4* __restrict__ oa,
                const float4* __restrict__ b, float4* __restrict__ ob, int n4)
{
    for (int i = blockIdx.x * 256 + threadIdx.x; i < n4; i += gridDim.x * 256) {
        float4 x = a[i];
        oa[i] = make_float4(tf32r(x.x), tf32r(x.y), tf32r(x.z), tf32r(x.w));
        float4 y = b[i];
        ob[i] = make_float4(tf32r(y.x), tf32r(y.y), tf32r(y.z), tf32r(y.w));
    }
}

__global__ void bias_concat(float* __restrict__ bc,
                            const float* kb1, const float* qb1, const float* vb1,
                            const float* kb2, const float* qb2, const float* vb2)
{
    const int i = threadIdx.x;
    bc[i]        = kb1[i]; bc[256 + i]  = qb1[i]; bc[512 + i]  = vb1[i];
    bc[768 + i]  = kb2[i]; bc[1024 + i] = qb2[i]; bc[1280 + i] = vb2[i];
}

// ---------------------------------------------------------------------------
// Host-side launch helper
// ---------------------------------------------------------------------------
template<int MUL, bool BIAS, bool RELU, bool BN, bool RNDC>
static void gemmNT(const float* A, size_t aB, int lda,
                   const float* B, size_t bB,
                   float* C, size_t cB, int M, int N, int K, int Z,
                   const float* bias, size_t biasB,
                   const float* mul, size_t mulB, float mulScale,
                   const float* gm, const float* bt,
                   const float* mn, const float* vr)
{
    cudaFuncSetAttribute(gemm_mma<MUL, BIAS, RELU, BN, RNDC>,
                         cudaFuncAttributeMaxDynamicSharedMemorySize, GEMM_SMEM_BYTES);
    dim3 grid(N / 128, M / 128, Z);
    gemm_mma<MUL, BIAS, RELU, BN, RNDC><<<grid, 256, GEMM_SMEM_BYTES>>>(
        A, aB, lda, B, bB, C, cB, M, N, K, bias, biasB, mul, mulB, mulScale, gm, bt, mn, vr);
}

extern "C" void kernel_launch(void* const* d_in, const int* in_sizes, int n_in,
                              void* d_out, int out_size)
{
    const float* seq1  = (const float*)d_in[0];
    const float* seq2  = (const float*)d_in[1];
    const float* disto = (const float*)d_in[2];
    const float* kW1 = (const float*)d_in[3];  const float* kb1 = (const float*)d_in[4];
    const float* kW2 = (const float*)d_in[5];  const float* kb2 = (const float*)d_in[6];
    const float* qW1 = (const float*)d_in[7];  const float* qb1 = (const float*)d_in[8];
    const float* qW2 = (const float*)d_in[9];  const float* qb2 = (const float*)d_in[10];
    const float* vW1 = (const float*)d_in[11]; const float* vb1 = (const float*)d_in[12];
    const float* vW2 = (const float*)d_in[13]; const float* vb2 = (const float*)d_in[14];
    const float* fc1W = (const float*)d_in[15]; const float* fc1b = (const float*)d_in[16];
    const float* fc2W = (const float*)d_in[17]; const float* fc2b = (const float*)d_in[18];
    const float* gma  = (const float*)d_in[19]; const float* bta  = (const float*)d_in[20];
    const float* mean = (const float*)d_in[21]; const float* var  = (const float*)d_in[22];
    float* out = (float*)d_out;

    float *h, *kqv1, *kqv2, *w1, *w2, *ap1, *ap2, *v1T, *v2T, *dT, *wT, *bc, *sr1, *sr2;
    cudaGetSymbolAddress((void**)&h,    g_h);
    cudaGetSymbolAddress((void**)&kqv1, g_kqv1);
    cudaGetSymbolAddress((void**)&kqv2, g_kqv2);
    cudaGetSymbolAddress((void**)&w1,   g_w1);
    cudaGetSymbolAddress((void**)&w2,   g_w2);
    cudaGetSymbolAddress((void**)&ap1,  g_ap1);
    cudaGetSymbolAddress((void**)&ap2,  g_ap2);
    cudaGetSymbolAddress((void**)&v1T,  g_v1T);
    cudaGetSymbolAddress((void**)&v2T,  g_v2T);
    cudaGetSymbolAddress((void**)&dT,   g_dT);
    cudaGetSymbolAddress((void**)&wT,   g_wT);
    cudaGetSymbolAddress((void**)&bc,   g_bc);
    cudaGetSymbolAddress((void**)&sr1,  g_sr1);
    cudaGetSymbolAddress((void**)&sr2,  g_sr2);

    const size_t seqB = (size_t)LDIM * SDIM;
    const size_t matB = (size_t)LDIM * LDIM;
    const int MFLAT = BATCH * LDIM;
    const float invS = 1.0f / 256.0f;

    float* h1 = h;
    float* h2 = h + HID_ELEMS;
    const float* k1 = kqv1;  const float* q1 = kqv1 + SEQ_ELEMS;  float* v1 = kqv1 + 2 * (size_t)SEQ_ELEMS;
    const float* k2 = kqv2;  const float* q2 = kqv2 + SEQ_ELEMS;  float* v2 = kqv2 + 2 * (size_t)SEQ_ELEMS;

    // (1) biases; (2) all weight transposes; (3) distogram transpose (exact);
    // (4) seq rounding  — then GEMMs occupy launch slots 5..8 for ncu.
    bias_concat<<<1, 256>>>(bc, kb1, qb1, vb1, kb2, qb2, vb2);
    wtrans8<<<dim3(8, 8, 8), dim3(32, 8)>>>(kW1, qW1, vW1, kW2, qW2, vW2, fc1W, fc2W, wT);
    transpose32<false><<<dim3(32, 32, BATCH), dim3(32, 8)>>>(disto, dT, LDIM, LDIM);
    round_seqs<<<1024, 256>>>((const float4*)seq1, (float4*)sr1,
                              (const float4*)seq2, (float4*)sr2, SEQ_ELEMS / 4);

    // (5-6) MLP layer 1 (fused k|q|v): h = relu(seq @ [kW1|qW1|vW1] + bc1), rounded
    gemmNT<0, true, true, false, true>(sr1, 0, 256, wT, 0, h1, 0, MFLAT, 768, 256, 1,
                                       bc, 0, nullptr, 0, 0.f, nullptr, nullptr, nullptr, nullptr);
    gemmNT<0, true, true, false, true>(sr2, 0, 256, wT, 0, h2, 0, MFLAT, 768, 256, 1,
                                       bc, 0, nullptr, 0, 0.f, nullptr, nullptr, nullptr, nullptr);
    // (7-8) MLP layer 2, grid.z = 3 (k,q,v), outputs rounded
    gemmNT<0, true, false, false, true>(h1, 256, 768, wT + 3 * 65536, 65536, kqv1, SEQ_ELEMS,
                                        MFLAT, 256, 256, 3, bc + 768, 256,
                                        nullptr, 0, 0.f, nullptr, nullptr, nullptr, nullptr);
    gemmNT<0, true, false, false, true>(h2, 256, 768, wT + 3 * 65536, 65536, kqv2, SEQ_ELEMS,
                                        MFLAT, 256, 256, 3, bc + 768, 256,
                                        nullptr, 0, 0.f, nullptr, nullptr, nullptr, nullptr);
    // (9-10) V transposes (rounded; inputs already rounded, idempotent)
    transpose32<true><<<dim3(8, 32, BATCH), dim3(32, 8)>>>(v1, v1T, LDIM, SDIM);
    transpose32<true><<<dim3(8, 32, BATCH), dim3(32, 8)>>>(v2, v2T, LDIM, SDIM);
    // (11-12) transposed scores (NOT rounded: feeds softmax, not MMA)
    gemmNT<1, false, false, false, false>(k2, seqB, 256, q1, seqB, w1, matB, LDIM, LDIM, SDIM, BATCH,
                                          nullptr, 0, dT, matB, invS, nullptr, nullptr, nullptr, nullptr);
    gemmNT<1, false, false, false, false>(k1, seqB, 256, q2, seqB, w2, matB, LDIM, LDIM, SDIM, BATCH,
                                          nullptr, 0, disto, matB, invS, nullptr, nullptr, nullptr, nullptr);
    // (13-14) softmax (outputs rounded)
    softmax_row<<<dim3(LDIM, BATCH), 256>>>(w1);
    softmax_row<<<dim3(LDIM, BATCH), 256>>>(w2);
    // (15-16) attention apply (outputs rounded: feed fc GEMM)
    gemmNT<0, false, false, false, true>(w1, matB, LDIM, v1T, seqB, ap1, seqB, LDIM, SDIM, LDIM, BATCH,
                                         nullptr, 0, nullptr, 0, 0.f, nullptr, nullptr, nullptr, nullptr);
    gemmNT<0, false, false, false, true>(w2, matB, LDIM, v2T, seqB, ap2, seqB, LDIM, SDIM, LDIM, BATCH,
                                         nullptr, 0, nullptr, 0, 0.f, nullptr, nullptr, nullptr, nullptr);
    // (17-18) output projections (final: NOT rounded)
    gemmNT<0, true, true, true, false>(ap1, 0, 256, wT + 6 * 65536, 0, out, 0, MFLAT, 256, 256, 1,
                                       fc1b, 0, nullptr, 0, 0.f, gma, bta, mean, var);
    gemmNT<0, true, true, true, false>(ap2, 0, 256, wT + 7 * 65536, 0, out + (size_t)SEQ_ELEMS, 0,
                                       MFLAT, 256, 256, 1, fc2b, 0, nullptr, 0, 0.f, gma, bta, mean, var);
}

// round 9
// speedup vs baseline: 4.0514x; 1.1455x over previous
#include <cuda_runtime.h>
#include <cuda_fp16.h>
#include <cstdint>
#include <math.h>

// ---------------------------------------------------------------------------
// Problem constants
// ---------------------------------------------------------------------------
#define BATCH 16
#define LDIM  1024
#define SDIM  256
#define EPS_BN 1e-3f

#define SEQ_ELEMS (BATCH * LDIM * SDIM)          // 4,194,304
#define MAT_ELEMS ((size_t)BATCH * LDIM * LDIM)  // 16,777,216
#define HID_ELEMS ((size_t)BATCH * LDIM * 768)

// Scratch (device globals: allocation-free, graph-capture safe)
__device__ float  g_sr [2 * (size_t)SEQ_ELEMS];  // tf32-rounded seq1|seq2
__device__ float  g_h  [2 * HID_ELEMS];          // layer-1 hidden
__device__ float  g_kqv[6 * (size_t)SEQ_ELEMS];  // k1,q1,v1,k2,q2,v2 (rounded)
__device__ float  g_w  [2 * MAT_ELEMS];          // s1t|s2t scores (fp32)
__device__ __half g_p  [2 * MAT_ELEMS];          // softmaxed P (fp16)
__device__ __half g_vTh[2 * (size_t)SEQ_ELEMS];  // transposed V (fp16)
__device__ float  g_ap [2 * (size_t)SEQ_ELEMS];  // attention outputs
__device__ float  g_dT [MAT_ELEMS];              // distogram transposed (exact)
__device__ float  g_wT [8 * 256 * 256];          // transposed weights (rounded)
__device__ float  g_bc [2 * 768];

// ---------------------------------------------------------------------------
__device__ __forceinline__ float tf32r(float x) {
    uint32_t u;
    asm("cvt.rna.tf32.f32 %0, %1;" : "=r"(u) : "f"(x));
    return __uint_as_float(u);
}
__device__ __forceinline__ uint32_t smem_u32(const void* p) {
    return (uint32_t)__cvta_generic_to_shared(p);
}
#define CP_ASYNC16(dst_u32, src_ptr) \
    asm volatile("cp.async.ca.shared.global [%0], [%1], 16;" \
                 :: "r"(dst_u32), "l"(src_ptr) : "memory")
#define CP_COMMIT() asm volatile("cp.async.commit_group;" ::: "memory")
#define CP_WAIT(n)  asm volatile("cp.async.wait_group %0;" :: "n"(n) : "memory")

// ---------------------------------------------------------------------------
// tf32 GEMM (cp.async 3-stage): C[z] = epi( A[z][M,K] @ B[z][N,K]^T )
// DUAL: z >= Zhalf switches to the second pointer set (z -= Zhalf).
// Operands must be pre-rounded to tf32 by producers.
// ---------------------------------------------------------------------------
#define NSTAGE 3
#define STG_FLOATS (128 * 32)
#define GEMM_SMEM_BYTES (NSTAGE * 2 * STG_FLOATS * 4)   // 96 KB

template<int MUL, bool BIAS, bool RELU, bool BN, bool RNDC, bool DUAL>
__global__ __launch_bounds__(256, 2)
void gemm_mma(const float* __restrict__ A, const float* __restrict__ A2,
              size_t aB, int lda,
              const float* __restrict__ B, const float* __restrict__ B2, size_t bB,
              float* __restrict__ C, float* __restrict__ C2, size_t cB,
              int M, int N, int K, int Zhalf,
              const float* __restrict__ bias, const float* __restrict__ bias2, size_t biasB,
              const float* __restrict__ mul, const float* __restrict__ mul2,
              size_t mulB, float mulScale,
              const float* __restrict__ gm, const float* __restrict__ bt,
              const float* __restrict__ mn, const float* __restrict__ vr)
{
    extern __shared__ float smem[];
    const int tid  = threadIdx.x;
    const int lane = tid & 31;
    const int wid  = tid >> 5;
    const int wm   = wid >> 2;
    const int wn   = wid & 3;
    int z = blockIdx.z;
    if (DUAL && z >= Zhalf) { A = A2; B = B2; C = C2; bias = bias2; mul = mul2; z -= Zhalf; }
    const int m0 = blockIdx.y * 128;
    const int n0 = blockIdx.x * 128;

    A += (size_t)z * aB + (size_t)m0 * lda;
    B += (size_t)z * bB + (size_t)n0 * K;
    C += (size_t)z * cB;
    if (BIAS) bias += (size_t)z * biasB;
    if (MUL)  mul  += (size_t)z * mulB;

    const uint32_t sbase = smem_u32(smem);

    float acc[4][4][4];
    #pragma unroll
    for (int i = 0; i < 4; i++)
        #pragma unroll
        for (int j = 0; j < 4; j++)
            #pragma unroll
            for (int t = 0; t < 4; t++) acc[i][j][t] = 0.f;

    const int nch = K >> 5;

    #define ISSUE(ck, p) do { \
        const uint32_t Ad = sbase + (uint32_t)(p) * (2 * STG_FLOATS * 4); \
        const uint32_t Bd = Ad + STG_FLOATS * 4; \
        const float* Ak = A + (ck) * 32; \
        const float* Bk = B + (ck) * 32; \
        _Pragma("unroll") \
        for (int it = 0; it < 4; ++it) { \
            const int qq = it * 256 + tid; \
            const int r  = qq >> 3, qi = qq & 7; \
            const uint32_t off = (uint32_t)(r * 32 + ((qi ^ (r & 7)) << 2)) * 4; \
            CP_ASYNC16(Ad + off, Ak + (size_t)r * lda + qi * 4); \
            CP_ASYNC16(Bd + off, Bk + (size_t)r * K   + qi * 4); \
        } \
        CP_COMMIT(); \
    } while (0)

    const int g  = lane >> 2;
    const int cc = lane & 3;

    ISSUE(0, 0);
    ISSUE(1, 1);

    for (int ch = 0; ch < nch; ++ch) {
        CP_WAIT(1);
        __syncthreads();
        if (ch + 2 < nch) ISSUE(ch + 2, (ch + 2) % NSTAGE);

        const float* Ab = smem + (ch % NSTAGE) * (2 * STG_FLOATS);
        const float* Bb = Ab + STG_FLOATS;

        #pragma unroll
        for (int s = 0; s < 4; ++s) {
            float a0[4], a1[4], a2[4], a3[4], b0[4], b1[4];
            #pragma unroll
            for (int i = 0; i < 4; ++i) {
                const int rA = wm * 64 + i * 16 + g;
                const int rA2 = rA + 8;
                a0[i] = Ab[rA  * 32 + (((2*s)     ^ (rA  & 7)) << 2) + cc];
                a2[i] = Ab[rA  * 32 + (((2*s + 1) ^ (rA  & 7)) << 2) + cc];
                a1[i] = Ab[rA2 * 32 + (((2*s)     ^ (rA2 & 7)) << 2) + cc];
                a3[i] = Ab[rA2 * 32 + (((2*s + 1) ^ (rA2 & 7)) << 2) + cc];
            }
            #pragma unroll
            for (int j = 0; j < 4; ++j) {
                const int rB = wn * 32 + j * 8 + g;
                b0[j] = Bb[rB * 32 + (((2*s)     ^ (rB & 7)) << 2) + cc];
                b1[j] = Bb[rB * 32 + (((2*s + 1) ^ (rB & 7)) << 2) + cc];
            }
            #pragma unroll
            for (int i = 0; i < 4; ++i)
                #pragma unroll
                for (int j = 0; j < 4; ++j) {
                    asm volatile(
                        "mma.sync.aligned.m16n8k8.row.col.f32.tf32.tf32.f32 "
                        "{%0,%1,%2,%3}, {%4,%5,%6,%7}, {%8,%9}, {%0,%1,%2,%3};"
                        : "+f"(acc[i][j][0]), "+f"(acc[i][j][1]),
                          "+f"(acc[i][j][2]), "+f"(acc[i][j][3])
                        : "r"(__float_as_uint(a0[i])), "r"(__float_as_uint(a1[i])),
                          "r"(__float_as_uint(a2[i])), "r"(__float_as_uint(a3[i])),
                          "r"(__float_as_uint(b0[j])), "r"(__float_as_uint(b1[j])));
                }
        }
        __syncthreads();
    }
    #undef ISSUE

    #pragma unroll
    for (int j = 0; j < 4; ++j) {
        const int col = n0 + wn * 32 + j * 8 + cc * 2;
        float2 b2, g2, be2, mn2, iv2;
        if (BIAS) b2 = *(const float2*)(bias + col);
        if (BN) {
            g2  = *(const float2*)(gm + col);
            be2 = *(const float2*)(bt + col);
            mn2 = *(const float2*)(mn + col);
            float2 v2 = *(const float2*)(vr + col);
            iv2 = make_float2(rsqrtf(v2.x + EPS_BN), rsqrtf(v2.y + EPS_BN));
        }
        #pragma unroll
        for (int i = 0; i < 4; ++i) {
            const int row0 = m0 + wm * 64 + i * 16 + g;
            #pragma unroll
            for (int hh = 0; hh < 2; ++hh) {
                const int row = row0 + hh * 8;
                float v0 = acc[i][j][hh * 2 + 0];
                float v1 = acc[i][j][hh * 2 + 1];
                if (BIAS) { v0 += b2.x; v1 += b2.y; }
                if (MUL) {
                    float2 m2 = *(const float2*)(mul + (size_t)row * N + col);
                    v0 *= m2.x * mulScale; v1 *= m2.y * mulScale;
                }
                if (RELU) { v0 = fmaxf(v0, 0.f); v1 = fmaxf(v1, 0.f); }
                if (BN) {
                    v0 = (v0 - mn2.x) * (g2.x * iv2.x) + be2.x;
                    v1 = (v1 - mn2.y) * (g2.y * iv2.y) + be2.y;
                }
                if (RNDC) { v0 = tf32r(v0); v1 = tf32r(v1); }
                *(float2*)(C + (size_t)row * N + col) = make_float2(v0, v1);
            }
        }
    }
}

// ---------------------------------------------------------------------------
// fp16 attention-apply GEMM: ap[z][1024,256] = P[z][1024,1024] @ Vt[z][256,1024]^T
// m16n8k16.f16 with fp32 accum; 3-stage cp.async; z>=16 -> second pair.
// Smem row = 32 halves (64 B) = 4 quads, swizzle: quad' = qi ^ ((r>>1)&3).
// Output tf32-rounded (feeds the fc tf32 GEMM).
// ---------------------------------------------------------------------------
#define F16_STG_WORDS 4096                       // (128+128) rows * 16 words
#define F16_SMEM_BYTES (NSTAGE * F16_STG_WORDS * 4)   // 48 KB

__global__ __launch_bounds__(256, 2)
void gemm_f16_apply(const __half* __restrict__ A, const __half* __restrict__ A2, size_t aB,
                    const __half* __restrict__ B, const __half* __restrict__ B2, size_t bB,
                    float* __restrict__ C, float* __restrict__ C2, size_t cB)
{
    extern __shared__ uint32_t smh[];
    const int tid  = threadIdx.x;
    const int lane = tid & 31;
    const int wid  = tid >> 5;
    const int wm   = wid >> 2;
    const int wn   = wid & 3;
    int z = blockIdx.z;
    if (z >= 16) { A = A2; B = B2; C = C2; z -= 16; }
    const int m0 = blockIdx.y * 128;
    const int n0 = blockIdx.x * 128;

    A += (size_t)z * aB + (size_t)m0 * 1024;
    B += (size_t)z * bB + (size_t)n0 * 1024;
    C += (size_t)z * cB;

    const uint32_t sbase = smem_u32(smh);

    float acc[4][4][4];
    #pragma unroll
    for (int i = 0; i < 4; i++)
        #pragma unroll
        for (int j = 0; j < 4; j++)
            #pragma unroll
            for (int t = 0; t < 4; t++) acc[i][j][t] = 0.f;

    #define ISSUEH(ck, p) do { \
        const uint32_t Ad = sbase + (uint32_t)(p) * (F16_STG_WORDS * 4); \
        const uint32_t Bd = Ad + 8192; \
        const __half* Ak = A + (ck) * 32; \
        const __half* Bk = B + (ck) * 32; \
        _Pragma("unroll") \
        for (int it = 0; it < 2; ++it) { \
            const int qq = it * 256 + tid; \
            const int r  = qq >> 2, qi = qq & 3; \
            const uint32_t off = (uint32_t)(r * 16 + ((qi ^ ((r >> 1) & 3)) << 2)) * 4; \
            CP_ASYNC16(Ad + off, Ak + (size_t)r * 1024 + qi * 8); \
            CP_ASYNC16(Bd + off, Bk + (size_t)r * 1024 + qi * 8); \
        } \
        CP_COMMIT(); \
    } while (0)

    const int g  = lane >> 2;
    const int cc = lane & 3;
    const int nch = 32;              // K = 1024

    ISSUEH(0, 0);
    ISSUEH(1, 1);

    for (int ch = 0; ch < nch; ++ch) {
        CP_WAIT(1);
        __syncthreads();
        if (ch + 2 < nch) ISSUEH(ch + 2, (ch + 2) % NSTAGE);

        const uint32_t* Ab = smh + (ch % NSTAGE) * F16_STG_WORDS;
        const uint32_t* Bb = Ab + 2048;

        #pragma unroll
        for (int s = 0; s < 2; ++s) {
            uint32_t a0[4], a1[4], a2[4], a3[4], b0[4], b1[4];
            #pragma unroll
            for (int i = 0; i < 4; ++i) {
                const int rA = wm * 64 + i * 16 + g;
                const int rA2 = rA + 8;
                a0[i] = Ab[rA  * 16 + (((2*s)     ^ ((rA  >> 1) & 3)) << 2) + cc];
                a2[i] = Ab[rA  * 16 + (((2*s + 1) ^ ((rA  >> 1) & 3)) << 2) + cc];
                a1[i] = Ab[rA2 * 16 + (((2*s)     ^ ((rA2 >> 1) & 3)) << 2) + cc];
                a3[i] = Ab[rA2 * 16 + (((2*s + 1) ^ ((rA2 >> 1) & 3)) << 2) + cc];
            }
            #pragma unroll
            for (int j = 0; j < 4; ++j) {
                const int rB = wn * 32 + j * 8 + g;
                b0[j] = Bb[rB * 16 + (((2*s)     ^ ((rB >> 1) & 3)) << 2) + cc];
                b1[j] = Bb[rB * 16 + (((2*s + 1) ^ ((rB >> 1) & 3)) << 2) + cc];
            }
            #pragma unroll
            for (int i = 0; i < 4; ++i)
                #pragma unroll
                for (int j = 0; j < 4; ++j) {
                    asm volatile(
                        "mma.sync.aligned.m16n8k16.row.col.f32.f16.f16.f32 "
                        "{%0,%1,%2,%3}, {%4,%5,%6,%7}, {%8,%9}, {%0,%1,%2,%3};"
                        : "+f"(acc[i][j][0]), "+f"(acc[i][j][1]),
                          "+f"(acc[i][j][2]), "+f"(acc[i][j][3])
                        : "r"(a0[i]), "r"(a1[i]), "r"(a2[i]), "r"(a3[i]),
                          "r"(b0[j]), "r"(b1[j]));
                }
        }
        __syncthreads();
    }
    #undef ISSUEH

    #pragma unroll
    for (int j = 0; j < 4; ++j) {
        const int col = n0 + wn * 32 + j * 8 + cc * 2;
        #pragma unroll
        for (int i = 0; i < 4; ++i) {
            const int row0 = m0 + wm * 64 + i * 16 + g;
            #pragma unroll
            for (int hh = 0; hh < 2; ++hh) {
                const int row = row0 + hh * 8;
                float v0 = tf32r(acc[i][j][hh * 2 + 0]);
                float v1 = tf32r(acc[i][j][hh * 2 + 1]);
                *(float2*)(C + (size_t)row * SDIM + col) = make_float2(v0, v1);
            }
        }
    }
}

// ---------------------------------------------------------------------------
// Row softmax over last axis of w[32 rows-of-batches...]: reads fp32 scores,
// writes fp16 P. grid = (LDIM, 32).
// ---------------------------------------------------------------------------
__global__ __launch_bounds__(256)
void softmax_row_h(const float* __restrict__ w, __half* __restrict__ p)
{
    __shared__ float s_max[8], s_sum[8];
    const size_t off = ((size_t)blockIdx.y * LDIM + blockIdx.x) * LDIM;
    const float* pw = w + off;
    __half2* pp = (__half2*)(p + off);
    const int t = threadIdx.x, wi = t >> 5, li = t & 31;

    float4 x = reinterpret_cast<const float4*>(pw)[t];
    float mx = fmaxf(fmaxf(x.x, x.y), fmaxf(x.z, x.w));
    #pragma unroll
    for (int o = 16; o; o >>= 1) mx = fmaxf(mx, __shfl_xor_sync(~0u, mx, o));
    if (li == 0) s_max[wi] = mx;
    __syncthreads();
    if (t == 0) {
        float v = s_max[0];
        #pragma unroll
        for (int i = 1; i < 8; i++) v = fmaxf(v, s_max[i]);
        s_max[0] = v;
    }
    __syncthreads();
    mx = s_max[0];
    float e0 = __expf(x.x - mx), e1 = __expf(x.y - mx);
    float e2 = __expf(x.z - mx), e3 = __expf(x.w - mx);
    float s = e0 + e1 + e2 + e3;
    #pragma unroll
    for (int o = 16; o; o >>= 1) s += __shfl_xor_sync(~0u, s, o);
    if (li == 0) s_sum[wi] = s;
    __syncthreads();
    if (t == 0) {
        float v = 0.f;
        #pragma unroll
        for (int i = 0; i < 8; i++) v += s_sum[i];
        s_sum[0] = v;
    }
    __syncthreads();
    const float inv = 1.0f / s_sum[0];
    pp[2 * t]     = __floats2half2_rn(e0 * inv, e1 * inv);
    pp[2 * t + 1] = __floats2half2_rn(e2 * inv, e3 * inv);
}

// ---------------------------------------------------------------------------
// V transpose to fp16: grid (8, 32, 32); z<16: v1 (kqv slab 2), else v2 (slab 5)
// ---------------------------------------------------------------------------
__global__ __launch_bounds__(256)
void vtrans_h(const float* __restrict__ kqv, __half* __restrict__ out)
{
    __shared__ float tile[32][33];
    const int z = blockIdx.z;
    const size_t seqB = (size_t)LDIM * SDIM;
    const float* in = kqv + (size_t)(z < 16 ? 2 : 5) * SEQ_ELEMS + (size_t)(z & 15) * seqB;
    __half* o = out + (size_t)(z < 16 ? 0 : 1) * SEQ_ELEMS + (size_t)(z & 15) * seqB;
    const int c0 = blockIdx.x * 32, r0 = blockIdx.y * 32;
    const int tx = threadIdx.x, ty = threadIdx.y;
    #pragma unroll
    for (int i = 0; i < 4; i++)
        tile[ty + 8 * i][tx] = in[(size_t)(r0 + ty + 8 * i) * SDIM + c0 + tx];
    __syncthreads();
    #pragma unroll
    for (int i = 0; i < 4; i++)
        o[(size_t)(c0 + ty + 8 * i) * LDIM + r0 + tx] = __float2half_rn(tile[tx][ty + 8 * i]);
}

// ---------------------------------------------------------------------------
template<bool RND>
__global__ __launch_bounds__(256)
void transpose32(const float* __restrict__ in, float* __restrict__ out, int R, int C)
{
    __shared__ float tile[32][33];
    const size_t zo = (size_t)blockIdx.z * (size_t)R * C;
    in += zo; out += zo;
    const int c0 = blockIdx.x * 32, r0 = blockIdx.y * 32;
    const int tx = threadIdx.x, ty = threadIdx.y;
    #pragma unroll
    for (int i = 0; i < 4; i++)
        tile[ty + 8 * i][tx] = in[(size_t)(r0 + ty + 8 * i) * C + c0 + tx];
    __syncthreads();
    #pragma unroll
    for (int i = 0; i < 4; i++) {
        float v = tile[tx][ty + 8 * i];
        out[(size_t)(c0 + ty + 8 * i) * R + r0 + tx] = RND ? tf32r(v) : v;
    }
}

__global__ __launch_bounds__(256)
void wtrans8(const float* w0, const float* w1, const float* w2, const float* w3,
             const float* w4, const float* w5, const float* w6, const float* w7,
             float* __restrict__ out)
{
    __shared__ float tile[32][33];
    const float* srcs[8] = {w0, w1, w2, w3, w4, w5, w6, w7};
    const float* in = srcs[blockIdx.z];
    float* o = out + (size_t)blockIdx.z * 65536;
    const int c0 = blockIdx.x * 32, r0 = blockIdx.y * 32;
    const int tx = threadIdx.x, ty = threadIdx.y;
    #pragma unroll
    for (int i = 0; i < 4; i++)
        tile[ty + 8 * i][tx] = in[(size_t)(r0 + ty + 8 * i) * 256 + c0 + tx];
    __syncthreads();
    #pragma unroll
    for (int i = 0; i < 4; i++)
        o[(size_t)(c0 + ty + 8 * i) * 256 + r0 + tx] = tf32r(tile[tx][ty + 8 * i]);
}

__global__ __launch_bounds__(256)
void round_seqs(const float4* __restrict__ a, float4* __restrict__ oa,
                const float4* __restrict__ b, float4* __restrict__ ob, int n4)
{
    for (int i = blockIdx.x * 256 + threadIdx.x; i < n4; i += gridDim.x * 256) {
        float4 x = a[i];
        oa[i] = make_float4(tf32r(x.x), tf32r(x.y), tf32r(x.z), tf32r(x.w));
        float4 y = b[i];
        ob[i] = make_float4(tf32r(y.x), tf32r(y.y), tf32r(y.z), tf32r(y.w));
    }
}

__global__ void bias_concat(float* __restrict__ bc,
                            const float* kb1, const float* qb1, const float* vb1,
                            const float* kb2, const float* qb2, const float* vb2)
{
    const int i = threadIdx.x;
    bc[i]        = kb1[i]; bc[256 + i]  = qb1[i]; bc[512 + i]  = vb1[i];
    bc[768 + i]  = kb2[i]; bc[1024 + i] = qb2[i]; bc[1280 + i] = vb2[i];
}

// ---------------------------------------------------------------------------
template<int MUL, bool BIAS, bool RELU, bool BN, bool RNDC, bool DUAL>
static void gemmNT(const float* A, const float* A2, size_t aB, int lda,
                   const float* B, const float* B2, size_t bB,
                   float* C, float* C2, size_t cB,
                   int M, int N, int K, int Z, int Zhalf,
                   const float* bias, const float* bias2, size_t biasB,
                   const float* mul, const float* mul2, size_t mulB, float mulScale,
                   const float* gm, const float* bt,
                   const float* mn, const float* vr)
{
    cudaFuncSetAttribute(gemm_mma<MUL, BIAS, RELU, BN, RNDC, DUAL>,
                         cudaFuncAttributeMaxDynamicSharedMemorySize, GEMM_SMEM_BYTES);
    dim3 grid(N / 128, M / 128, Z);
    gemm_mma<MUL, BIAS, RELU, BN, RNDC, DUAL><<<grid, 256, GEMM_SMEM_BYTES>>>(
        A, A2, aB, lda, B, B2, bB, C, C2, cB, M, N, K, Zhalf,
        bias, bias2, biasB, mul, mul2, mulB, mulScale, gm, bt, mn, vr);
}

extern "C" void kernel_launch(void* const* d_in, const int* in_sizes, int n_in,
                              void* d_out, int out_size)
{
    const float* seq1  = (const float*)d_in[0];
    const float* seq2  = (const float*)d_in[1];
    const float* disto = (const float*)d_in[2];
    const float* kW1 = (const float*)d_in[3];  const float* kb1 = (const float*)d_in[4];
    const float* kW2 = (const float*)d_in[5];  const float* kb2 = (const float*)d_in[6];
    const float* qW1 = (const float*)d_in[7];  const float* qb1 = (const float*)d_in[8];
    const float* qW2 = (const float*)d_in[9];  const float* qb2 = (const float*)d_in[10];
    const float* vW1 = (const float*)d_in[11]; const float* vb1 = (const float*)d_in[12];
    const float* vW2 = (const float*)d_in[13]; const float* vb2 = (const float*)d_in[14];
    const float* fc1W = (const float*)d_in[15]; const float* fc1b = (const float*)d_in[16];
    const float* fc2W = (const float*)d_in[17]; const float* fc2b = (const float*)d_in[18];
    const float* gma  = (const float*)d_in[19]; const float* bta  = (const float*)d_in[20];
    const float* mean = (const float*)d_in[21]; const float* var  = (const float*)d_in[22];
    float* out = (float*)d_out;

    float *sr, *h, *kqv, *w, *ap, *dT, *wT, *bc;
    __half *p, *vTh;
    cudaGetSymbolAddress((void**)&sr,  g_sr);
    cudaGetSymbolAddress((void**)&h,   g_h);
    cudaGetSymbolAddress((void**)&kqv, g_kqv);
    cudaGetSymbolAddress((void**)&w,   g_w);
    cudaGetSymbolAddress((void**)&p,   g_p);
    cudaGetSymbolAddress((void**)&vTh, g_vTh);
    cudaGetSymbolAddress((void**)&ap,  g_ap);
    cudaGetSymbolAddress((void**)&dT,  g_dT);
    cudaGetSymbolAddress((void**)&wT,  g_wT);
    cudaGetSymbolAddress((void**)&bc,  g_bc);

    const size_t seqB = (size_t)LDIM * SDIM;
    const size_t matB = (size_t)LDIM * LDIM;
    const int MFLAT = BATCH * LDIM;
    const float invS = 1.0f / 256.0f;

    // (0) biases  (1) weight transposes  (2) seq rounding
    bias_concat<<<1, 256>>>(bc, kb1, qb1, vb1, kb2, qb2, vb2);
    wtrans8<<<dim3(8, 8, 8), dim3(32, 8)>>>(kW1, qW1, vW1, kW2, qW2, vW2, fc1W, fc2W, wT);
    round_seqs<<<1024, 256>>>((const float4*)seq1, (float4*)sr,
                              (const float4*)seq2, (float4*)(sr + SEQ_ELEMS), SEQ_ELEMS / 4);
    // (3) MLP layer 1, both seqs in one launch (z=2)
    gemmNT<0, true, true, false, true, false>(
        sr, nullptr, (size_t)SEQ_ELEMS, 256, wT, nullptr, 0,
        h, nullptr, HID_ELEMS, MFLAT, 768, 256, 2, 0,
        bc, nullptr, 0, nullptr, nullptr, 0, 0.f, nullptr, nullptr, nullptr, nullptr);
    // (4) distogram transpose (exact fp32)
    transpose32<false><<<dim3(32, 32, BATCH), dim3(32, 8)>>>(disto, dT, LDIM, LDIM);
    // (5) MLP layer 2, both seqs, k/q/v: z=6, DUAL at 3
    gemmNT<0, true, false, false, true, true>(
        h, h + HID_ELEMS, 256, 768,
        wT + 3 * 65536, wT + 3 * 65536, 65536,
        kqv, kqv + 3 * (size_t)SEQ_ELEMS, (size_t)SEQ_ELEMS,
        MFLAT, 256, 256, 6, 3,
        bc + 768, bc + 768, 256, nullptr, nullptr, 0, 0.f,
        nullptr, nullptr, nullptr, nullptr);
    // (6) V transposes to fp16, both (z=32)
    vtrans_h<<<dim3(8, 32, 32), dim3(32, 8)>>>(kqv, vTh);
    // (7) scores, both (z=32, DUAL at 16):
    //   z<16:  s1t = (k2 . q1) * dT    / 256
    //   z>=16: s2t = (k1 . q2) * disto / 256
    gemmNT<1, false, false, false, false, true>(
        kqv + 3 * (size_t)SEQ_ELEMS, kqv, seqB, 256,
        kqv + (size_t)SEQ_ELEMS, kqv + 4 * (size_t)SEQ_ELEMS, seqB,
        w, w + MAT_ELEMS, matB,
        LDIM, LDIM, SDIM, 32, 16,
        nullptr, nullptr, 0, dT, disto, matB, invS,
        nullptr, nullptr, nullptr, nullptr);
    // (8) softmax -> fp16 P, both tensors (grid.y = 32)
    softmax_row_h<<<dim3(LDIM, 32), 256>>>(w, p);
    // (9) fp16 attention apply, both (z=32)
    {
        cudaFuncSetAttribute(gemm_f16_apply,
                             cudaFuncAttributeMaxDynamicSharedMemorySize, F16_SMEM_BYTES);
        dim3 grid(SDIM / 128, LDIM / 128, 32);
        gemm_f16_apply<<<grid, 256, F16_SMEM_BYTES>>>(
            p, p + MAT_ELEMS, matB, vTh, vTh + SEQ_ELEMS, seqB,
            ap, ap + (size_t)SEQ_ELEMS, seqB);
    }
    // (10) output projections, both (z=2, DUAL at 1)
    gemmNT<0, true, true, true, false, true>(
        ap, ap + (size_t)SEQ_ELEMS, 0, 256,
        wT + 6 * 65536, wT + 7 * 65536, 0,
        out, out + (size_t)SEQ_ELEMS, 0,
        MFLAT, 256, 256, 2, 1,
        fc1b, fc2b, 0, nullptr, nullptr, 0, 0.f,
        gma, bta, mean, var);
}

// round 11
// speedup vs baseline: 5.3934x; 1.3312x over previous
#include <cuda_runtime.h>
#include <cuda_fp16.h>
#include <cstdint>
#include <math.h>

// ---------------------------------------------------------------------------
#define BATCH 16
#define LDIM  1024
#define SDIM  256
#define EPS_BN 1e-3f

#define SEQ_ELEMS (BATCH * LDIM * SDIM)          // 4,194,304
#define MAT_ELEMS ((size_t)BATCH * LDIM * LDIM)  // 16,777,216
#define HID_ELEMS ((size_t)BATCH * LDIM * 768)

// Scratch (device globals)
__device__ __half g_srh [2 * (size_t)SEQ_ELEMS]; // fp16 seq1|seq2
__device__ __half g_hh  [2 * HID_ELEMS];         // fp16 layer-1 hidden
__device__ __half g_kqvh[6 * (size_t)SEQ_ELEMS]; // fp16 k1,q1,v1,k2,q2,v2
__device__ float  g_w   [2 * MAT_ELEMS];         // fp32 scores s1t|s2t
__device__ __half g_p   [2 * MAT_ELEMS];         // fp16 softmaxed P
__device__ __half g_vTh [2 * (size_t)SEQ_ELEMS]; // fp16 transposed V
__device__ __half g_aph [2 * (size_t)SEQ_ELEMS]; // fp16 attention outputs
__device__ float  g_dT  [MAT_ELEMS];             // fp32 distogram transposed
__device__ __half g_wTh [8 * 256 * 256];         // fp16 transposed weights
__device__ float  g_bc  [2 * 768];               // fp32 concat biases

// ---------------------------------------------------------------------------
__device__ __forceinline__ uint32_t smem_u32(const void* p) {
    return (uint32_t)__cvta_generic_to_shared(p);
}
#define CP_ASYNC16(dst_u32, src_ptr) \
    asm volatile("cp.async.ca.shared.global [%0], [%1], 16;" \
                 :: "r"(dst_u32), "l"(src_ptr) : "memory")
#define CP_COMMIT() asm volatile("cp.async.commit_group;" ::: "memory")
#define CP_WAIT(n)  asm volatile("cp.async.wait_group %0;" :: "n"(n) : "memory")

// ---------------------------------------------------------------------------
// Unified fp16 GEMM (cp.async 3-stage): C[z] = epi( A[z][M,K] @ B[z][N,K]^T )
// m16n8k16.f16 with fp32 accum. CTA 128x128, K-chunk 32, 8 warps (2Mx4N).
// Smem row = 32 halves (16 words, 64B); quad qi of row r at (qi ^ ((r>>1)&3)).
// DUAL: z >= Zhalf switches to the second pointer set.
// Epilogue fp32: +bias -> *mul*mulScale -> relu -> batchnorm; out half or float.
// ---------------------------------------------------------------------------
#define NSTAGE 3
#define H_STG_WORDS 4096                          // (128+128) rows * 16 words
#define H_SMEM_BYTES (NSTAGE * H_STG_WORDS * 4)   // 48 KB

template<int MUL, bool BIAS, bool RELU, bool BN, bool OUTH, bool DUAL>
__global__ __launch_bounds__(256, 2)
void gemm_h(const __half* __restrict__ A, const __half* __restrict__ A2,
            size_t aB, int lda,
            const __half* __restrict__ B, const __half* __restrict__ B2, size_t bB,
            void* __restrict__ Cv, void* __restrict__ Cv2, size_t cB,
            int M, int N, int K, int Zhalf,
            const float* __restrict__ bias, const float* __restrict__ bias2, size_t biasB,
            const float* __restrict__ mul, const float* __restrict__ mul2,
            size_t mulB, float mulScale,
            const float* __restrict__ gm, const float* __restrict__ bt,
            const float* __restrict__ mn, const float* __restrict__ vr)
{
    extern __shared__ uint32_t smh[];
    const int tid  = threadIdx.x;
    const int lane = tid & 31;
    const int wid  = tid >> 5;
    const int wm   = wid >> 2;
    const int wn   = wid & 3;
    int z = blockIdx.z;
    void* Cp = Cv;
    if (DUAL && z >= Zhalf) {
        A = A2; B = B2; Cp = Cv2; bias = bias2; mul = mul2; z -= Zhalf;
    }
    const int m0 = blockIdx.y * 128;
    const int n0 = blockIdx.x * 128;

    A += (size_t)z * aB + (size_t)m0 * lda;
    B += (size_t)z * bB + (size_t)n0 * K;
    if (BIAS) bias += (size_t)z * biasB;
    if (MUL)  mul  += (size_t)z * mulB;
    const size_t cOff = (size_t)z * cB;

    const uint32_t sbase = smem_u32(smh);

    float acc[4][4][4];
    #pragma unroll
    for (int i = 0; i < 4; i++)
        #pragma unroll
        for (int j = 0; j < 4; j++)
            #pragma unroll
            for (int t = 0; t < 4; t++) acc[i][j][t] = 0.f;

    const int nch = K >> 5;

    #define ISSUEH(ck, p) do { \
        const uint32_t Ad = sbase + (uint32_t)(p) * (H_STG_WORDS * 4); \
        const uint32_t Bd = Ad + 8192; \
        const __half* Ak = A + (ck) * 32; \
        const __half* Bk = B + (ck) * 32; \
        _Pragma("unroll") \
        for (int it = 0; it < 2; ++it) { \
            const int qq = it * 256 + tid; \
            const int r  = qq >> 2, qi = qq & 3; \
            const uint32_t off = (uint32_t)(r * 16 + ((qi ^ ((r >> 1) & 3)) << 2)) * 4; \
            CP_ASYNC16(Ad + off, Ak + (size_t)r * lda + qi * 8); \
            CP_ASYNC16(Bd + off, Bk + (size_t)r * K   + qi * 8); \
        } \
        CP_COMMIT(); \
    } while (0)

    const int g  = lane >> 2;
    const int cc = lane & 3;

    ISSUEH(0, 0);
    if (nch > 1) ISSUEH(1, 1);

    for (int ch = 0; ch < nch; ++ch) {
        if (ch + 1 < nch) { CP_WAIT(1); } else { CP_WAIT(0); }
        __syncthreads();
        if (ch + 2 < nch) ISSUEH(ch + 2, (ch + 2) % NSTAGE);

        const uint32_t* Ab = smh + (ch % NSTAGE) * H_STG_WORDS;
        const uint32_t* Bb = Ab + 2048;

        #pragma unroll
        for (int s = 0; s < 2; ++s) {
            uint32_t a0[4], a1[4], a2[4], a3[4], b0[4], b1[4];
            #pragma unroll
            for (int i = 0; i < 4; ++i) {
                const int rA = wm * 64 + i * 16 + g;
                const int rA2 = rA + 8;
                a0[i] = Ab[rA  * 16 + (((2*s)     ^ ((rA  >> 1) & 3)) << 2) + cc];
                a2[i] = Ab[rA  * 16 + (((2*s + 1) ^ ((rA  >> 1) & 3)) << 2) + cc];
                a1[i] = Ab[rA2 * 16 + (((2*s)     ^ ((rA2 >> 1) & 3)) << 2) + cc];
                a3[i] = Ab[rA2 * 16 + (((2*s + 1) ^ ((rA2 >> 1) & 3)) << 2) + cc];
            }
            #pragma unroll
            for (int j = 0; j < 4; ++j) {
                const int rB = wn * 32 + j * 8 + g;
                b0[j] = Bb[rB * 16 + (((2*s)     ^ ((rB >> 1) & 3)) << 2) + cc];
                b1[j] = Bb[rB * 16 + (((2*s + 1) ^ ((rB >> 1) & 3)) << 2) + cc];
            }
            #pragma unroll
            for (int i = 0; i < 4; ++i)
                #pragma unroll
                for (int j = 0; j < 4; ++j) {
                    asm volatile(
                        "mma.sync.aligned.m16n8k16.row.col.f32.f16.f16.f32 "
                        "{%0,%1,%2,%3}, {%4,%5,%6,%7}, {%8,%9}, {%0,%1,%2,%3};"
                        : "+f"(acc[i][j][0]), "+f"(acc[i][j][1]),
                          "+f"(acc[i][j][2]), "+f"(acc[i][j][3])
                        : "r"(a0[i]), "r"(a1[i]), "r"(a2[i]), "r"(a3[i]),
                          "r"(b0[j]), "r"(b1[j]));
                }
        }
        __syncthreads();
    }
    #undef ISSUEH

    // ---- epilogue (fp32 math) ----
    #pragma unroll
    for (int j = 0; j < 4; ++j) {
        const int col = n0 + wn * 32 + j * 8 + cc * 2;
        float2 b2, g2, be2, mn2, iv2;
        if (BIAS) b2 = *(const float2*)(bias + col);
        if (BN) {
            g2  = *(const float2*)(gm + col);
            be2 = *(const float2*)(bt + col);
            mn2 = *(const float2*)(mn + col);
            float2 v2 = *(const float2*)(vr + col);
            iv2 = make_float2(rsqrtf(v2.x + EPS_BN), rsqrtf(v2.y + EPS_BN));
        }
        #pragma unroll
        for (int i = 0; i < 4; ++i) {
            const int row0 = m0 + wm * 64 + i * 16 + g;
            #pragma unroll
            for (int hh = 0; hh < 2; ++hh) {
                const int row = row0 + hh * 8;
                float v0 = acc[i][j][hh * 2 + 0];
                float v1 = acc[i][j][hh * 2 + 1];
                if (BIAS) { v0 += b2.x; v1 += b2.y; }
                if (MUL) {
                    float2 m2 = *(const float2*)(mul + (size_t)row * N + col);
                    v0 *= m2.x * mulScale; v1 *= m2.y * mulScale;
                }
                if (RELU) { v0 = fmaxf(v0, 0.f); v1 = fmaxf(v1, 0.f); }
                if (BN) {
                    v0 = (v0 - mn2.x) * (g2.x * iv2.x) + be2.x;
                    v1 = (v1 - mn2.y) * (g2.y * iv2.y) + be2.y;
                }
                if (OUTH) {
                    __half* Ch = (__half*)Cp + cOff;
                    *(__half2*)(Ch + (size_t)row * N + col) = __floats2half2_rn(v0, v1);
                } else {
                    float* Cf = (float*)Cp + cOff;
                    *(float2*)(Cf + (size_t)row * N + col) = make_float2(v0, v1);
                }
            }
        }
    }
}

// ---------------------------------------------------------------------------
// Row softmax (fp32 scores -> fp16 P). grid = (LDIM, 32).
// ---------------------------------------------------------------------------
__global__ __launch_bounds__(256)
void softmax_row_h(const float* __restrict__ w, __half* __restrict__ p)
{
    __shared__ float s_max[8], s_sum[8];
    const size_t off = ((size_t)blockIdx.y * LDIM + blockIdx.x) * LDIM;
    const float* pw = w + off;
    __half2* pp = (__half2*)(p + off);
    const int t = threadIdx.x, wi = t >> 5, li = t & 31;

    float4 x = reinterpret_cast<const float4*>(pw)[t];
    float mx = fmaxf(fmaxf(x.x, x.y), fmaxf(x.z, x.w));
    #pragma unroll
    for (int o = 16; o; o >>= 1) mx = fmaxf(mx, __shfl_xor_sync(~0u, mx, o));
    if (li == 0) s_max[wi] = mx;
    __syncthreads();
    if (t == 0) {
        float v = s_max[0];
        #pragma unroll
        for (int i = 1; i < 8; i++) v = fmaxf(v, s_max[i]);
        s_max[0] = v;
    }
    __syncthreads();
    mx = s_max[0];
    float e0 = __expf(x.x - mx), e1 = __expf(x.y - mx);
    float e2 = __expf(x.z - mx), e3 = __expf(x.w - mx);
    float s = e0 + e1 + e2 + e3;
    #pragma unroll
    for (int o = 16; o; o >>= 1) s += __shfl_xor_sync(~0u, s, o);
    if (li == 0) s_sum[wi] = s;
    __syncthreads();
    if (t == 0) {
        float v = 0.f;
        #pragma unroll
        for (int i = 0; i < 8; i++) v += s_sum[i];
        s_sum[0] = v;
    }
    __syncthreads();
    const float inv = 1.0f / s_sum[0];
    pp[2 * t]     = __floats2half2_rn(e0 * inv, e1 * inv);
    pp[2 * t + 1] = __floats2half2_rn(e2 * inv, e3 * inv);
}

// ---------------------------------------------------------------------------
// V transpose (fp16 -> fp16): grid (8, 32, 32); z<16: v1 (slab 2), else v2 (5)
// ---------------------------------------------------------------------------
__global__ __launch_bounds__(256)
void vtrans_h(const __half* __restrict__ kqvh, __half* __restrict__ out)
{
    __shared__ __half tile[32][34];
    const int z = blockIdx.z;
    const size_t seqB = (size_t)LDIM * SDIM;
    const __half* in = kqvh + (size_t)(z < 16 ? 2 : 5) * SEQ_ELEMS + (size_t)(z & 15) * seqB;
    __half* o = out + (size_t)(z < 16 ? 0 : 1) * SEQ_ELEMS + (size_t)(z & 15) * seqB;
    const int c0 = blockIdx.x * 32, r0 = blockIdx.y * 32;
    const int tx = threadIdx.x, ty = threadIdx.y;
    #pragma unroll
    for (int i = 0; i < 4; i++)
        tile[ty + 8 * i][tx] = in[(size_t)(r0 + ty + 8 * i) * SDIM + c0 + tx];
    __syncthreads();
    #pragma unroll
    for (int i = 0; i < 4; i++)
        o[(size_t)(c0 + ty + 8 * i) * LDIM + r0 + tx] = tile[tx][ty + 8 * i];
}

// ---------------------------------------------------------------------------
// fp32 transpose (distogram, exact)
// ---------------------------------------------------------------------------
__global__ __launch_bounds__(256)
void transpose32f(const float* __restrict__ in, float* __restrict__ out, int R, int C)
{
    __shared__ float tile[32][33];
    const size_t zo = (size_t)blockIdx.z * (size_t)R * C;
    in += zo; out += zo;
    const int c0 = blockIdx.x * 32, r0 = blockIdx.y * 32;
    const int tx = threadIdx.x, ty = threadIdx.y;
    #pragma unroll
    for (int i = 0; i < 4; i++)
        tile[ty + 8 * i][tx] = in[(size_t)(r0 + ty + 8 * i) * C + c0 + tx];
    __syncthreads();
    #pragma unroll
    for (int i = 0; i < 4; i++)
        out[(size_t)(c0 + ty + 8 * i) * R + r0 + tx] = tile[tx][ty + 8 * i];
}

// ---------------------------------------------------------------------------
// Transpose all 8 weight matrices to fp16 in one launch.
// ---------------------------------------------------------------------------
__global__ __launch_bounds__(256)
void wtrans8h(const float* w0, const float* w1, const float* w2, const float* w3,
              const float* w4, const float* w5, const float* w6, const float* w7,
              __half* __restrict__ out)
{
    __shared__ float tile[32][33];
    const float* srcs[8] = {w0, w1, w2, w3, w4, w5, w6, w7};
    const float* in = srcs[blockIdx.z];
    __half* o = out + (size_t)blockIdx.z * 65536;
    const int c0 = blockIdx.x * 32, r0 = blockIdx.y * 32;
    const int tx = threadIdx.x, ty = threadIdx.y;
    #pragma unroll
    for (int i = 0; i < 4; i++)
        tile[ty + 8 * i][tx] = in[(size_t)(r0 + ty + 8 * i) * 256 + c0 + tx];
    __syncthreads();
    #pragma unroll
    for (int i = 0; i < 4; i++)
        o[(size_t)(c0 + ty + 8 * i) * 256 + r0 + tx] = __float2half_rn(tile[tx][ty + 8 * i]);
}

// ---------------------------------------------------------------------------
// fp16-convert both seq tensors
// ---------------------------------------------------------------------------
__global__ __launch_bounds__(256)
void seqs_to_h(const float4* __restrict__ a, __half2* __restrict__ oa,
               const float4* __restrict__ b, __half2* __restrict__ ob, int n4)
{
    for (int i = blockIdx.x * 256 + threadIdx.x; i < n4; i += gridDim.x * 256) {
        float4 x = a[i];
        oa[2 * i]     = __floats2half2_rn(x.x, x.y);
        oa[2 * i + 1] = __floats2half2_rn(x.z, x.w);
        float4 y = b[i];
        ob[2 * i]     = __floats2half2_rn(y.x, y.y);
        ob[2 * i + 1] = __floats2half2_rn(y.z, y.w);
    }
}

__global__ void bias_concat(float* __restrict__ bc,
                            const float* kb1, const float* qb1, const float* vb1,
                            const float* kb2, const float* qb2, const float* vb2)
{
    const int i = threadIdx.x;
    bc[i]        = kb1[i]; bc[256 + i]  = qb1[i]; bc[512 + i]  = vb1[i];
    bc[768 + i]  = kb2[i]; bc[1024 + i] = qb2[i]; bc[1280 + i] = vb2[i];
}

// ---------------------------------------------------------------------------
template<int MUL, bool BIAS, bool RELU, bool BN, bool OUTH, bool DUAL>
static void gemmH(const __half* A, const __half* A2, size_t aB, int lda,
                  const __half* B, const __half* B2, size_t bB,
                  void* C, void* C2, size_t cB,
                  int M, int N, int K, int Z, int Zhalf,
                  const float* bias, const float* bias2, size_t biasB,
                  const float* mul, const float* mul2, size_t mulB, float mulScale,
                  const float* gm, const float* bt,
                  const float* mn, const float* vr)
{
    cudaFuncSetAttribute(gemm_h<MUL, BIAS, RELU, BN, OUTH, DUAL>,
                         cudaFuncAttributeMaxDynamicSharedMemorySize, H_SMEM_BYTES);
    dim3 grid(N / 128, M / 128, Z);
    gemm_h<MUL, BIAS, RELU, BN, OUTH, DUAL><<<grid, 256, H_SMEM_BYTES>>>(
        A, A2, aB, lda, B, B2, bB, C, C2, cB, M, N, K, Zhalf,
        bias, bias2, biasB, mul, mul2, mulB, mulScale, gm, bt, mn, vr);
}

extern "C" void kernel_launch(void* const* d_in, const int* in_sizes, int n_in,
                              void* d_out, int out_size)
{
    const float* seq1  = (const float*)d_in[0];
    const float* seq2  = (const float*)d_in[1];
    const float* disto = (const float*)d_in[2];
    const float* kW1 = (const float*)d_in[3];  const float* kb1 = (const float*)d_in[4];
    const float* kW2 = (const float*)d_in[5];  const float* kb2 = (const float*)d_in[6];
    const float* qW1 = (const float*)d_in[7];  const float* qb1 = (const float*)d_in[8];
    const float* qW2 = (const float*)d_in[9];  const float* qb2 = (const float*)d_in[10];
    const float* vW1 = (const float*)d_in[11]; const float* vb1 = (const float*)d_in[12];
    const float* vW2 = (const float*)d_in[13]; const float* vb2 = (const float*)d_in[14];
    const float* fc1W = (const float*)d_in[15]; const float* fc1b = (const float*)d_in[16];
    const float* fc2W = (const float*)d_in[17]; const float* fc2b = (const float*)d_in[18];
    const float* gma  = (const float*)d_in[19]; const float* bta  = (const float*)d_in[20];
    const float* mean = (const float*)d_in[21]; const float* var  = (const float*)d_in[22];
    float* out = (float*)d_out;

    __half *srh, *hh, *kqvh, *p, *vTh, *aph, *wTh;
    float *w, *dT, *bc;
    cudaGetSymbolAddress((void**)&srh,  g_srh);
    cudaGetSymbolAddress((void**)&hh,   g_hh);
    cudaGetSymbolAddress((void**)&kqvh, g_kqvh);
    cudaGetSymbolAddress((void**)&w,    g_w);
    cudaGetSymbolAddress((void**)&p,    g_p);
    cudaGetSymbolAddress((void**)&vTh,  g_vTh);
    cudaGetSymbolAddress((void**)&aph,  g_aph);
    cudaGetSymbolAddress((void**)&dT,   g_dT);
    cudaGetSymbolAddress((void**)&wTh,  g_wTh);
    cudaGetSymbolAddress((void**)&bc,   g_bc);

    const size_t seqB = (size_t)LDIM * SDIM;
    const size_t matB = (size_t)LDIM * LDIM;
    const int MFLAT = BATCH * LDIM;
    const float invS = 1.0f / 256.0f;

    // (0) biases  (1) weight transposes  (2) seq fp16 conversion
    bias_concat<<<1, 256>>>(bc, kb1, qb1, vb1, kb2, qb2, vb2);
    wtrans8h<<<dim3(8, 8, 8), dim3(32, 8)>>>(kW1, qW1, vW1, kW2, qW2, vW2, fc1W, fc2W, wTh);
    seqs_to_h<<<1024, 256>>>((const float4*)seq1, (__half2*)srh,
                             (const float4*)seq2, (__half2*)(srh + SEQ_ELEMS), SEQ_ELEMS / 4);
    // (3) MLP layer 1, both seqs (z=2): hh = relu(seq @ [kW1|qW1|vW1] + bc1)
    gemmH<0, true, true, false, true, false>(
        srh, nullptr, (size_t)SEQ_ELEMS, 256, wTh, nullptr, 0,
        hh, nullptr, HID_ELEMS, MFLAT, 768, 256, 2, 0,
        bc, nullptr, 0, nullptr, nullptr, 0, 0.f, nullptr, nullptr, nullptr, nullptr);
    // (4) distogram transpose (exact fp32)
    transpose32f<<<dim3(32, 32, BATCH), dim3(32, 8)>>>(disto, dT, LDIM, LDIM);
    // (5) MLP layer 2, both seqs, k/q/v (z=6, DUAL at 3)
    gemmH<0, true, false, false, true, true>(
        hh, hh + HID_ELEMS, 256, 768,
        wTh + 3 * 65536, wTh + 3 * 65536, 65536,
        kqvh, kqvh + 3 * (size_t)SEQ_ELEMS, (size_t)SEQ_ELEMS,
        MFLAT, 256, 256, 6, 3,
        bc + 768, bc + 768, 256, nullptr, nullptr, 0, 0.f,
        nullptr, nullptr, nullptr, nullptr);
    // (6) V transposes (fp16), both (z=32)
    vtrans_h<<<dim3(8, 32, 32), dim3(32, 8)>>>(kqvh, vTh);
    // (7) scores, both (z=32, DUAL at 16), fp32 out:
    //   z<16:  s1t = (k2 . q1) * dT    / 256
    //   z>=16: s2t = (k1 . q2) * disto / 256
    gemmH<1, false, false, false, false, true>(
        kqvh + 3 * (size_t)SEQ_ELEMS, kqvh, seqB, 256,
        kqvh + (size_t)SEQ_ELEMS, kqvh + 4 * (size_t)SEQ_ELEMS, seqB,
        w, w + MAT_ELEMS, matB,
        LDIM, LDIM, SDIM, 32, 16,
        nullptr, nullptr, 0, dT, disto, matB, invS,
        nullptr, nullptr, nullptr, nullptr);
    // (8) softmax -> fp16 P, both tensors
    softmax_row_h<<<dim3(LDIM, 32), 256>>>(w, p);
    // (9) attention apply, both (z=32, DUAL at 16), fp16 out
    gemmH<0, false, false, false, true, true>(
        p, p + MAT_ELEMS, matB, 1024,
        vTh, vTh + SEQ_ELEMS, seqB,
        aph, aph + (size_t)SEQ_ELEMS, seqB,
        LDIM, SDIM, LDIM, 32, 16,
        nullptr, nullptr, 0, nullptr, nullptr, 0, 0.f,
        nullptr, nullptr, nullptr, nullptr);
    // (10) output projections, both (z=2, DUAL at 1), fp32 out with BN
    gemmH<0, true, true, true, false, true>(
        aph, aph + (size_t)SEQ_ELEMS, 0, 256,
        wTh + 6 * 65536, wTh + 7 * 65536, 0,
        out, out + (size_t)SEQ_ELEMS, 0,
        MFLAT, 256, 256, 2, 1,
        fc1b, fc2b, 0, nullptr, nullptr, 0, 0.f,
        gma, bta, mean, var);
}

// round 12
// speedup vs baseline: 5.4152x; 1.0040x over previous
#include <cuda_runtime.h>
#include <cuda_fp16.h>
#include <cstdint>
#include <math.h>

// ---------------------------------------------------------------------------
#define BATCH 16
#define LDIM  1024
#define SDIM  256
#define EPS_BN 1e-3f

#define SEQ_ELEMS (BATCH * LDIM * SDIM)          // 4,194,304
#define MAT_ELEMS ((size_t)BATCH * LDIM * LDIM)  // 16,777,216
#define HID_ELEMS ((size_t)BATCH * LDIM * 768)

// Scratch (device globals)
__device__ __half g_srh [2 * (size_t)SEQ_ELEMS]; // fp16 seq1|seq2
__device__ __half g_hh  [2 * HID_ELEMS];         // fp16 layer-1 hidden
__device__ __half g_kqvh[6 * (size_t)SEQ_ELEMS]; // fp16 k1,q1,v1,k2,q2,v2
__device__ __half g_w   [2 * MAT_ELEMS];         // fp16 scores s1t|s2t
__device__ __half g_p   [2 * MAT_ELEMS];         // fp16 softmaxed P
__device__ __half g_vTh [2 * (size_t)SEQ_ELEMS]; // fp16 transposed V
__device__ __half g_aph [2 * (size_t)SEQ_ELEMS]; // fp16 attention outputs
__device__ __half g_dh  [MAT_ELEMS];             // fp16 distogram
__device__ __half g_dTh [MAT_ELEMS];             // fp16 distogram transposed
__device__ __half g_wTh [8 * 256 * 256];         // fp16 transposed weights
__device__ float  g_bc  [2 * 768];               // fp32 concat biases

// ---------------------------------------------------------------------------
__device__ __forceinline__ uint32_t smem_u32(const void* p) {
    return (uint32_t)__cvta_generic_to_shared(p);
}
#define CP_ASYNC16(dst_u32, src_ptr) \
    asm volatile("cp.async.ca.shared.global [%0], [%1], 16;" \
                 :: "r"(dst_u32), "l"(src_ptr) : "memory")
#define CP_COMMIT() asm volatile("cp.async.commit_group;" ::: "memory")
#define CP_WAIT(n)  asm volatile("cp.async.wait_group %0;" :: "n"(n) : "memory")

// ---------------------------------------------------------------------------
// Unified fp16 GEMM (cp.async 5-stage): C[z] = epi( A[z][M,K] @ B[z][N,K]^T )
// m16n8k16.f16, fp32 accum. CTA 128x128, K-chunk 32, 8 warps (2Mx4N).
// Smem row = 32 halves (16 words); quad qi of row r at (qi ^ ((r>>1)&3)).
// DUAL: z >= Zhalf switches pointer sets. Requires K >= 128 (nch >= 4).
// Epilogue fp32: +bias -> *mul(half)*mulScale -> relu -> BN; out half/float.
// ---------------------------------------------------------------------------
#define NSTAGE 5
#define H_STG_WORDS 4096                          // (128+128) rows * 16 words
#define H_SMEM_BYTES (NSTAGE * H_STG_WORDS * 4)   // 80 KB

template<int MUL, bool BIAS, bool RELU, bool BN, bool OUTH, bool DUAL>
__global__ __launch_bounds__(256, 2)
void gemm_h(const __half* __restrict__ A, const __half* __restrict__ A2,
            size_t aB, int lda,
            const __half* __restrict__ B, const __half* __restrict__ B2, size_t bB,
            void* __restrict__ Cv, void* __restrict__ Cv2, size_t cB,
            int M, int N, int K, int Zhalf,
            const float* __restrict__ bias, const float* __restrict__ bias2, size_t biasB,
            const __half* __restrict__ mul, const __half* __restrict__ mul2,
            size_t mulB, float mulScale,
            const float* __restrict__ gm, const float* __restrict__ bt,
            const float* __restrict__ mn, const float* __restrict__ vr)
{
    extern __shared__ uint32_t smh[];
    const int tid  = threadIdx.x;
    const int lane = tid & 31;
    const int wid  = tid >> 5;
    const int wm   = wid >> 2;
    const int wn   = wid & 3;
    int z = blockIdx.z;
    void* Cp = Cv;
    if (DUAL && z >= Zhalf) {
        A = A2; B = B2; Cp = Cv2; bias = bias2; mul = mul2; z -= Zhalf;
    }
    const int m0 = blockIdx.y * 128;
    const int n0 = blockIdx.x * 128;

    A += (size_t)z * aB + (size_t)m0 * lda;
    B += (size_t)z * bB + (size_t)n0 * K;
    if (BIAS) bias += (size_t)z * biasB;
    if (MUL)  mul  += (size_t)z * mulB;
    const size_t cOff = (size_t)z * cB;

    const uint32_t sbase = smem_u32(smh);

    float acc[4][4][4];
    #pragma unroll
    for (int i = 0; i < 4; i++)
        #pragma unroll
        for (int j = 0; j < 4; j++)
            #pragma unroll
            for (int t = 0; t < 4; t++) acc[i][j][t] = 0.f;

    const int nch = K >> 5;

    #define ISSUEH(ck, p) do { \
        const uint32_t Ad = sbase + (uint32_t)(p) * (H_STG_WORDS * 4); \
        const uint32_t Bd = Ad + 8192; \
        const __half* Ak = A + (ck) * 32; \
        const __half* Bk = B + (ck) * 32; \
        _Pragma("unroll") \
        for (int it = 0; it < 2; ++it) { \
            const int qq = it * 256 + tid; \
            const int r  = qq >> 2, qi = qq & 3; \
            const uint32_t off = (uint32_t)(r * 16 + ((qi ^ ((r >> 1) & 3)) << 2)) * 4; \
            CP_ASYNC16(Ad + off, Ak + (size_t)r * lda + qi * 8); \
            CP_ASYNC16(Bd + off, Bk + (size_t)r * K   + qi * 8); \
        } \
        CP_COMMIT(); \
    } while (0)

    const int g  = lane >> 2;
    const int cc = lane & 3;

    // prologue: fill 4 stages (requires nch >= 4; all uses have nch >= 8)
    ISSUEH(0, 0); ISSUEH(1, 1); ISSUEH(2, 2); ISSUEH(3, 3);

    for (int ch = 0; ch < nch; ++ch) {
        const int rem = nch - 1 - ch;   // groups committed younger than ch
        if (rem >= 3)      { CP_WAIT(3); }
        else if (rem == 2) { CP_WAIT(2); }
        else if (rem == 1) { CP_WAIT(1); }
        else               { CP_WAIT(0); }
        __syncthreads();
        if (ch + 4 < nch) ISSUEH(ch + 4, (ch + 4) % NSTAGE);

        const uint32_t* Ab = smh + (ch % NSTAGE) * H_STG_WORDS;
        const uint32_t* Bb = Ab + 2048;

        #pragma unroll
        for (int s = 0; s < 2; ++s) {
            uint32_t a0[4], a1[4], a2[4], a3[4], b0[4], b1[4];
            #pragma unroll
            for (int i = 0; i < 4; ++i) {
                const int rA = wm * 64 + i * 16 + g;
                const int rA2 = rA + 8;
                a0[i] = Ab[rA  * 16 + (((2*s)     ^ ((rA  >> 1) & 3)) << 2) + cc];
                a2[i] = Ab[rA  * 16 + (((2*s + 1) ^ ((rA  >> 1) & 3)) << 2) + cc];
                a1[i] = Ab[rA2 * 16 + (((2*s)     ^ ((rA2 >> 1) & 3)) << 2) + cc];
                a3[i] = Ab[rA2 * 16 + (((2*s + 1) ^ ((rA2 >> 1) & 3)) << 2) + cc];
            }
            #pragma unroll
            for (int j = 0; j < 4; ++j) {
                const int rB = wn * 32 + j * 8 + g;
                b0[j] = Bb[rB * 16 + (((2*s)     ^ ((rB >> 1) & 3)) << 2) + cc];
                b1[j] = Bb[rB * 16 + (((2*s + 1) ^ ((rB >> 1) & 3)) << 2) + cc];
            }
            #pragma unroll
            for (int i = 0; i < 4; ++i)
                #pragma unroll
                for (int j = 0; j < 4; ++j) {
                    asm volatile(
                        "mma.sync.aligned.m16n8k16.row.col.f32.f16.f16.f32 "
                        "{%0,%1,%2,%3}, {%4,%5,%6,%7}, {%8,%9}, {%0,%1,%2,%3};"
                        : "+f"(acc[i][j][0]), "+f"(acc[i][j][1]),
                          "+f"(acc[i][j][2]), "+f"(acc[i][j][3])
                        : "r"(a0[i]), "r"(a1[i]), "r"(a2[i]), "r"(a3[i]),
                          "r"(b0[j]), "r"(b1[j]));
                }
        }
        __syncthreads();
    }
    #undef ISSUEH

    // ---- epilogue (fp32 math) ----
    #pragma unroll
    for (int j = 0; j < 4; ++j) {
        const int col = n0 + wn * 32 + j * 8 + cc * 2;
        float2 b2, g2, be2, mn2, iv2;
        if (BIAS) b2 = *(const float2*)(bias + col);
        if (BN) {
            g2  = *(const float2*)(gm + col);
            be2 = *(const float2*)(bt + col);
            mn2 = *(const float2*)(mn + col);
            float2 v2 = *(const float2*)(vr + col);
            iv2 = make_float2(rsqrtf(v2.x + EPS_BN), rsqrtf(v2.y + EPS_BN));
        }
        #pragma unroll
        for (int i = 0; i < 4; ++i) {
            const int row0 = m0 + wm * 64 + i * 16 + g;
            #pragma unroll
            for (int hh = 0; hh < 2; ++hh) {
                const int row = row0 + hh * 8;
                float v0 = acc[i][j][hh * 2 + 0];
                float v1 = acc[i][j][hh * 2 + 1];
                if (BIAS) { v0 += b2.x; v1 += b2.y; }
                if (MUL) {
                    __half2 mh = *(const __half2*)(mul + (size_t)row * N + col);
                    float2 m2 = __half22float2(mh);
                    v0 *= m2.x * mulScale; v1 *= m2.y * mulScale;
                }
                if (RELU) { v0 = fmaxf(v0, 0.f); v1 = fmaxf(v1, 0.f); }
                if (BN) {
                    v0 = (v0 - mn2.x) * (g2.x * iv2.x) + be2.x;
                    v1 = (v1 - mn2.y) * (g2.y * iv2.y) + be2.y;
                }
                if (OUTH) {
                    __half* Ch = (__half*)Cp + cOff;
                    *(__half2*)(Ch + (size_t)row * N + col) = __floats2half2_rn(v0, v1);
                } else {
                    float* Cf = (float*)Cp + cOff;
                    *(float2*)(Cf + (size_t)row * N + col) = make_float2(v0, v1);
                }
            }
        }
    }
}

// ---------------------------------------------------------------------------
// Row softmax (fp16 scores -> fp16 P). grid = (LDIM, 32).
// ---------------------------------------------------------------------------
__global__ __launch_bounds__(256)
void softmax_row_h(const __half* __restrict__ w, __half* __restrict__ p)
{
    __shared__ float s_max[8], s_sum[8];
    const size_t off = ((size_t)blockIdx.y * LDIM + blockIdx.x) * LDIM;
    const __half2* pw = (const __half2*)(w + off);
    __half2* pp = (__half2*)(p + off);
    const int t = threadIdx.x, wi = t >> 5, li = t & 31;

    float2 xa = __half22float2(pw[2 * t]);
    float2 xb = __half22float2(pw[2 * t + 1]);
    float mx = fmaxf(fmaxf(xa.x, xa.y), fmaxf(xb.x, xb.y));
    #pragma unroll
    for (int o = 16; o; o >>= 1) mx = fmaxf(mx, __shfl_xor_sync(~0u, mx, o));
    if (li == 0) s_max[wi] = mx;
    __syncthreads();
    if (t == 0) {
        float v = s_max[0];
        #pragma unroll
        for (int i = 1; i < 8; i++) v = fmaxf(v, s_max[i]);
        s_max[0] = v;
    }
    __syncthreads();
    mx = s_max[0];
    float e0 = __expf(xa.x - mx), e1 = __expf(xa.y - mx);
    float e2 = __expf(xb.x - mx), e3 = __expf(xb.y - mx);
    float s = e0 + e1 + e2 + e3;
    #pragma unroll
    for (int o = 16; o; o >>= 1) s += __shfl_xor_sync(~0u, s, o);
    if (li == 0) s_sum[wi] = s;
    __syncthreads();
    if (t == 0) {
        float v = 0.f;
        #pragma unroll
        for (int i = 0; i < 8; i++) v += s_sum[i];
        s_sum[0] = v;
    }
    __syncthreads();
    const float inv = 1.0f / s_sum[0];
    pp[2 * t]     = __floats2half2_rn(e0 * inv, e1 * inv);
    pp[2 * t + 1] = __floats2half2_rn(e2 * inv, e3 * inv);
}

// ---------------------------------------------------------------------------
// V transpose (fp16 -> fp16): grid (8, 32, 32); z<16: v1 (slab 2), else v2 (5)
// ---------------------------------------------------------------------------
__global__ __launch_bounds__(256)
void vtrans_h(const __half* __restrict__ kqvh, __half* __restrict__ out)
{
    __shared__ __half tile[32][34];
    const int z = blockIdx.z;
    const size_t seqB = (size_t)LDIM * SDIM;
    const __half* in = kqvh + (size_t)(z < 16 ? 2 : 5) * SEQ_ELEMS + (size_t)(z & 15) * seqB;
    __half* o = out + (size_t)(z < 16 ? 0 : 1) * SEQ_ELEMS + (size_t)(z & 15) * seqB;
    const int c0 = blockIdx.x * 32, r0 = blockIdx.y * 32;
    const int tx = threadIdx.x, ty = threadIdx.y;
    #pragma unroll
    for (int i = 0; i < 4; i++)
        tile[ty + 8 * i][tx] = in[(size_t)(r0 + ty + 8 * i) * SDIM + c0 + tx];
    __syncthreads();
    #pragma unroll
    for (int i = 0; i < 4; i++)
        o[(size_t)(c0 + ty + 8 * i) * LDIM + r0 + tx] = tile[tx][ty + 8 * i];
}

// ---------------------------------------------------------------------------
// Distogram -> fp16 straight copy + fp16 transpose. grid (32, 32, 16).
// ---------------------------------------------------------------------------
__global__ __launch_bounds__(256)
void disto_conv(const float* __restrict__ in, __half* __restrict__ dh,
                __half* __restrict__ dTh)
{
    __shared__ __half tile[32][34];
    const size_t zo = (size_t)blockIdx.z * (size_t)LDIM * LDIM;
    in += zo; dh += zo; dTh += zo;
    const int c0 = blockIdx.x * 32, r0 = blockIdx.y * 32;
    const int tx = threadIdx.x, ty = threadIdx.y;
    #pragma unroll
    for (int i = 0; i < 4; i++) {
        const int r = r0 + ty + 8 * i;
        __half v = __float2half_rn(in[(size_t)r * LDIM + c0 + tx]);
        dh[(size_t)r * LDIM + c0 + tx] = v;
        tile[ty + 8 * i][tx] = v;
    }
    __syncthreads();
    #pragma unroll
    for (int i = 0; i < 4; i++)
        dTh[(size_t)(c0 + ty + 8 * i) * LDIM + r0 + tx] = tile[tx][ty + 8 * i];
}

// ---------------------------------------------------------------------------
// Transpose all 8 weight matrices to fp16 in one launch.
// ---------------------------------------------------------------------------
__global__ __launch_bounds__(256)
void wtrans8h(const float* w0, const float* w1, const float* w2, const float* w3,
              const float* w4, const float* w5, const float* w6, const float* w7,
              __half* __restrict__ out)
{
    __shared__ float tile[32][33];
    const float* srcs[8] = {w0, w1, w2, w3, w4, w5, w6, w7};
    const float* in = srcs[blockIdx.z];
    __half* o = out + (size_t)blockIdx.z * 65536;
    const int c0 = blockIdx.x * 32, r0 = blockIdx.y * 32;
    const int tx = threadIdx.x, ty = threadIdx.y;
    #pragma unroll
    for (int i = 0; i < 4; i++)
        tile[ty + 8 * i][tx] = in[(size_t)(r0 + ty + 8 * i) * 256 + c0 + tx];
    __syncthreads();
    #pragma unroll
    for (int i = 0; i < 4; i++)
        o[(size_t)(c0 + ty + 8 * i) * 256 + r0 + tx] = __float2half_rn(tile[tx][ty + 8 * i]);
}

// ---------------------------------------------------------------------------
// fp16-convert both seq tensors
// ---------------------------------------------------------------------------
__global__ __launch_bounds__(256)
void seqs_to_h(const float4* __restrict__ a, __half2* __restrict__ oa,
               const float4* __restrict__ b, __half2* __restrict__ ob, int n4)
{
    for (int i = blockIdx.x * 256 + threadIdx.x; i < n4; i += gridDim.x * 256) {
        float4 x = a[i];
        oa[2 * i]     = __floats2half2_rn(x.x, x.y);
        oa[2 * i + 1] = __floats2half2_rn(x.z, x.w);
        float4 y = b[i];
        ob[2 * i]     = __floats2half2_rn(y.x, y.y);
        ob[2 * i + 1] = __floats2half2_rn(y.z, y.w);
    }
}

__global__ void bias_concat(float* __restrict__ bc,
                            const float* kb1, const float* qb1, const float* vb1,
                            const float* kb2, const float* qb2, const float* vb2)
{
    const int i = threadIdx.x;
    bc[i]        = kb1[i]; bc[256 + i]  = qb1[i]; bc[512 + i]  = vb1[i];
    bc[768 + i]  = kb2[i]; bc[1024 + i] = qb2[i]; bc[1280 + i] = vb2[i];
}

// ---------------------------------------------------------------------------
template<int MUL, bool BIAS, bool RELU, bool BN, bool OUTH, bool DUAL>
static void gemmH(const __half* A, const __half* A2, size_t aB, int lda,
                  const __half* B, const __half* B2, size_t bB,
                  void* C, void* C2, size_t cB,
                  int M, int N, int K, int Z, int Zhalf,
                  const float* bias, const float* bias2, size_t biasB,
                  const __half* mul, const __half* mul2, size_t mulB, float mulScale,
                  const float* gm, const float* bt,
                  const float* mn, const float* vr)
{
    cudaFuncSetAttribute(gemm_h<MUL, BIAS, RELU, BN, OUTH, DUAL>,
                         cudaFuncAttributeMaxDynamicSharedMemorySize, H_SMEM_BYTES);
    dim3 grid(N / 128, M / 128, Z);
    gemm_h<MUL, BIAS, RELU, BN, OUTH, DUAL><<<grid, 256, H_SMEM_BYTES>>>(
        A, A2, aB, lda, B, B2, bB, C, C2, cB, M, N, K, Zhalf,
        bias, bias2, biasB, mul, mul2, mulB, mulScale, gm, bt, mn, vr);
}

extern "C" void kernel_launch(void* const* d_in, const int* in_sizes, int n_in,
                              void* d_out, int out_size)
{
    const float* seq1  = (const float*)d_in[0];
    const float* seq2  = (const float*)d_in[1];
    const float* disto = (const float*)d_in[2];
    const float* kW1 = (const float*)d_in[3];  const float* kb1 = (const float*)d_in[4];
    const float* kW2 = (const float*)d_in[5];  const float* kb2 = (const float*)d_in[6];
    const float* qW1 = (const float*)d_in[7];  const float* qb1 = (const float*)d_in[8];
    const float* qW2 = (const float*)d_in[9];  const float* qb2 = (const float*)d_in[10];
    const float* vW1 = (const float*)d_in[11]; const float* vb1 = (const float*)d_in[12];
    const float* vW2 = (const float*)d_in[13]; const float* vb2 = (const float*)d_in[14];
    const float* fc1W = (const float*)d_in[15]; const float* fc1b = (const float*)d_in[16];
    const float* fc2W = (const float*)d_in[17]; const float* fc2b = (const float*)d_in[18];
    const float* gma  = (const float*)d_in[19]; const float* bta  = (const float*)d_in[20];
    const float* mean = (const float*)d_in[21]; const float* var  = (const float*)d_in[22];
    float* out = (float*)d_out;

    __half *srh, *hh, *kqvh, *wsc, *p, *vTh, *aph, *dh, *dTh, *wTh;
    float *bc;
    cudaGetSymbolAddress((void**)&srh,  g_srh);
    cudaGetSymbolAddress((void**)&hh,   g_hh);
    cudaGetSymbolAddress((void**)&kqvh, g_kqvh);
    cudaGetSymbolAddress((void**)&wsc,  g_w);
    cudaGetSymbolAddress((void**)&p,    g_p);
    cudaGetSymbolAddress((void**)&vTh,  g_vTh);
    cudaGetSymbolAddress((void**)&aph,  g_aph);
    cudaGetSymbolAddress((void**)&dh,   g_dh);
    cudaGetSymbolAddress((void**)&dTh,  g_dTh);
    cudaGetSymbolAddress((void**)&wTh,  g_wTh);
    cudaGetSymbolAddress((void**)&bc,   g_bc);

    const size_t seqB = (size_t)LDIM * SDIM;
    const size_t matB = (size_t)LDIM * LDIM;
    const int MFLAT = BATCH * LDIM;
    const float invS = 1.0f / 256.0f;

    // (0) biases  (1) weight transposes  (2) seq fp16 conversion
    bias_concat<<<1, 256>>>(bc, kb1, qb1, vb1, kb2, qb2, vb2);
    wtrans8h<<<dim3(8, 8, 8), dim3(32, 8)>>>(kW1, qW1, vW1, kW2, qW2, vW2, fc1W, fc2W, wTh);
    seqs_to_h<<<1024, 256>>>((const float4*)seq1, (__half2*)srh,
                             (const float4*)seq2, (__half2*)(srh + SEQ_ELEMS), SEQ_ELEMS / 4);
    // (3) MLP layer 1, both seqs (z=2)
    gemmH<0, true, true, false, true, false>(
        srh, nullptr, (size_t)SEQ_ELEMS, 256, wTh, nullptr, 0,
        hh, nullptr, HID_ELEMS, MFLAT, 768, 256, 2, 0,
        bc, nullptr, 0, nullptr, nullptr, 0, 0.f, nullptr, nullptr, nullptr, nullptr);
    // (4) distogram -> fp16 copy + transpose
    disto_conv<<<dim3(32, 32, BATCH), dim3(32, 8)>>>(disto, dh, dTh);
    // (5) MLP layer 2, both seqs, k/q/v (z=6, DUAL at 3)
    gemmH<0, true, false, false, true, true>(
        hh, hh + HID_ELEMS, 256, 768,
        wTh + 3 * 65536, wTh + 3 * 65536, 65536,
        kqvh, kqvh + 3 * (size_t)SEQ_ELEMS, (size_t)SEQ_ELEMS,
        MFLAT, 256, 256, 6, 3,
        bc + 768, bc + 768, 256, nullptr, nullptr, 0, 0.f,
        nullptr, nullptr, nullptr, nullptr);
    // (6) V transposes (fp16), both (z=32)
    vtrans_h<<<dim3(8, 32, 32), dim3(32, 8)>>>(kqvh, vTh);
    // (7) scores, both (z=32, DUAL at 16), fp16 out:
    //   z<16:  s1t = (k2 . q1) * dTh / 256
    //   z>=16: s2t = (k1 . q2) * dh  / 256
    gemmH<1, false, false, false, true, true>(
        kqvh + 3 * (size_t)SEQ_ELEMS, kqvh, seqB, 256,
        kqvh + (size_t)SEQ_ELEMS, kqvh + 4 * (size_t)SEQ_ELEMS, seqB,
        wsc, wsc + MAT_ELEMS, matB,
        LDIM, LDIM, SDIM, 32, 16,
        nullptr, nullptr, 0, dTh, dh, matB, invS,
        nullptr, nullptr, nullptr, nullptr);
    // (8) softmax (fp16 in) -> fp16 P, both tensors
    softmax_row_h<<<dim3(LDIM, 32), 256>>>(wsc, p);
    // (9) attention apply, both (z=32, DUAL at 16), fp16 out
    gemmH<0, false, false, false, true, true>(
        p, p + MAT_ELEMS, matB, 1024,
        vTh, vTh + SEQ_ELEMS, seqB,
        aph, aph + (size_t)SEQ_ELEMS, seqB,
        LDIM, SDIM, LDIM, 32, 16,
        nullptr, nullptr, 0, nullptr, nullptr, 0, 0.f,
        nullptr, nullptr, nullptr, nullptr);
    // (10) output projections, both (z=2, DUAL at 1), fp32 out with BN
    gemmH<0, true, true, true, false, true>(
        aph, aph + (size_t)SEQ_ELEMS, 0, 256,
        wTh + 6 * 65536, wTh + 7 * 65536, 0,
        out, out + (size_t)SEQ_ELEMS, 0,
        MFLAT, 256, 256, 2, 1,
        fc1b, fc2b, 0, nullptr, nullptr, 0, 0.f,
        gma, bta, mean, var);
}